// round 1
// baseline (speedup 1.0000x reference)
#include <cuda_runtime.h>
#include <math.h>
#include <stdint.h>
#include <stddef.h>

// ---------------- problem constants ----------------
#define NUM_B 4
#define SEQ   2048
#define DIM   512
#define NH    8
#define DHD   64
#define FF    2048
#define ROWS  (NUM_B*SEQ)          // 8192
#define NLAYER 2

// output layout (float32, concatenated in reference return order)
#define OFF_XT   0
#define N_XT     (ROWS*DIM)                 // 4194304
#define OFF_IDS  (OFF_XT + N_XT)            // 4194304
#define N_IDS    (ROWS)                     // 8192
#define OFF_ACL  (OFF_IDS + N_IDS)          // 4202496
#define OFF_MASK (OFF_ACL + 1)              // 4202497 (odd -> scalar stores only)
#define N_MASK   (NUM_B*SEQ*SEQ)            // 16777216
#define OFF_CLL  (OFF_MASK + N_MASK)        // 20979713

// ---------------- scratch (device globals; no allocation allowed) ----------------
__device__ float g_X [ROWS*DIM];
__device__ float g_Hn[ROWS*DIM];
__device__ float g_Ql[ROWS*DIM];
__device__ float g_Kl[ROWS*DIM];
__device__ float g_Vl[ROWS*DIM];
__device__ float g_Qr[ROWS*DIM];
__device__ float g_Kr[ROWS*DIM];
__device__ float g_Vr[ROWS*DIM];
__device__ float g_O [ROWS*DIM];
__device__ float g_G [ROWS*FF];
__device__ float g_probs[ROWS];
__device__ int   g_ids[ROWS];
__device__ int   g_nch[NUM_B];
__device__ float g_psum[NUM_B];

// ---------------- rmsnorm: one block per row (D=512, 256 threads) ----------------
__global__ void rmsnorm_kernel(const float* __restrict__ x, const float* __restrict__ w,
                               float* __restrict__ out) {
    int row = blockIdx.x;
    int t = threadIdx.x;
    const float* xr = x + (size_t)row * DIM;
    float v0 = xr[t], v1 = xr[t + 256];
    __shared__ float red[256];
    red[t] = v0 * v0 + v1 * v1;
    __syncthreads();
#pragma unroll
    for (int o = 128; o > 0; o >>= 1) {
        if (t < o) red[t] += red[t + o];
        __syncthreads();
    }
    float inv = rsqrtf(red[0] * (1.0f / (float)DIM) + 1e-6f);
    float* orow = out + (size_t)row * DIM;
    orow[t]       = v0 * inv * w[t];
    orow[t + 256] = v1 * inv * w[t + 256];
}

// ---------------- SGEMM: C[M,N] = A[M,K] @ B[K,N] (+epilogue) ----------------
// 64x64 tile, BK=16, 256 threads, 4x4 microtile. M,N,K multiples of 64/64/16.
// EPI: 0 none, 1 add Cin (residual; Cin may alias C), 2 exact gelu
template<int EPI>
__global__ void sgemm_kernel(const float* __restrict__ A, const float* __restrict__ B,
                             const float* Cin, float* C, int M, int N, int K) {
    __shared__ float As[16][65];
    __shared__ float Bs[16][65];
    int bm = blockIdx.y * 64, bn = blockIdx.x * 64;
    int t = threadIdx.x;
    int ty = t >> 4, tx = t & 15;
    int a_row = t >> 2, a_k = (t & 3) << 2;
    int b_k = t >> 4, b_n = (t & 15) << 2;
    float acc[4][4] = {};
    for (int k0 = 0; k0 < K; k0 += 16) {
        float4 av = *(const float4*)(A + (size_t)(bm + a_row) * K + k0 + a_k);
        As[a_k + 0][a_row] = av.x; As[a_k + 1][a_row] = av.y;
        As[a_k + 2][a_row] = av.z; As[a_k + 3][a_row] = av.w;
        float4 bv = *(const float4*)(B + (size_t)(k0 + b_k) * N + bn + b_n);
        Bs[b_k][b_n + 0] = bv.x; Bs[b_k][b_n + 1] = bv.y;
        Bs[b_k][b_n + 2] = bv.z; Bs[b_k][b_n + 3] = bv.w;
        __syncthreads();
#pragma unroll
        for (int kk = 0; kk < 16; kk++) {
            float a[4], bb[4];
#pragma unroll
            for (int i = 0; i < 4; i++) a[i] = As[kk][ty * 4 + i];
#pragma unroll
            for (int j = 0; j < 4; j++) bb[j] = Bs[kk][tx * 4 + j];
#pragma unroll
            for (int i = 0; i < 4; i++)
#pragma unroll
                for (int j = 0; j < 4; j++)
                    acc[i][j] = fmaf(a[i], bb[j], acc[i][j]);
        }
        __syncthreads();
    }
#pragma unroll
    for (int i = 0; i < 4; i++) {
        int row = bm + ty * 4 + i;
#pragma unroll
        for (int j = 0; j < 4; j++) {
            int col = bn + tx * 4 + j;
            float v = acc[i][j];
            if (EPI == 1) v += Cin[(size_t)row * N + col];
            if (EPI == 2) v = 0.5f * v * (1.0f + erff(v * 0.70710678118654752f));
            C[(size_t)row * N + col] = v;
        }
    }
}

// ---------------- rope + head-transpose: (B,S,H*Dh) -> (B,H,S,Dh) ----------------
__global__ void rope_kernel(const float* __restrict__ lin, float* __restrict__ out) {
    int bs = blockIdx.x;              // b*SEQ + s
    int s = bs & (SEQ - 1);
    int b = bs >> 11;
    int h = threadIdx.x >> 5;
    int i = threadIdx.x & 31;
    const float* src = lin + (size_t)bs * DIM + h * DHD;
    float t1 = src[i], t2 = src[i + 32];
    double inv = pow(10000.0, -(double)i / 32.0);
    double ang = (double)s * inv;
    double cs, sn;
    sincos(ang, &sn, &cs);
    float c = (float)cs, si = (float)sn;
    float* dst = out + (((size_t)(b * NH + h)) * SEQ + s) * DHD;
    dst[i]      = t1 * c - t2 * si;
    dst[i + 32] = t1 * si + t2 * c;
}

__global__ void vtrans_kernel(const float* __restrict__ lin, float* __restrict__ out) {
    int bs = blockIdx.x;
    int s = bs & (SEQ - 1);
    int b = bs >> 11;
    int t = threadIdx.x;
    for (int e = t; e < DIM; e += 256) {
        int h = e >> 6, d = e & 63;
        out[(((size_t)(b * NH + h)) * SEQ + s) * DHD + d] = lin[(size_t)bs * DIM + e];
    }
}

// ---------------- flash attention: 64 q-rows per CTA, causal, online softmax ----------------
#define ATT_SMEM ((3*64*65 + 64*64 + 3*64) * 4)   // 67072 bytes

__global__ void attention_kernel(const float* __restrict__ Q, const float* __restrict__ K,
                                 const float* __restrict__ V, float* __restrict__ O) {
    extern __shared__ float sm[];
    float* Qs = sm;                 // 64 x 65
    float* Ks = Qs + 64 * 65;       // 64 x 65
    float* Ss = Ks + 64 * 65;       // 64 x 65  (scores / probs)
    float* Vs = Ss + 64 * 65;       // 64 x 64  (16B-aligned base)
    float* rowM = Vs + 64 * 64;
    float* rowL = rowM + 64;
    float* rowF = rowL + 64;
    int bh = blockIdx.y;
    int qt = blockIdx.x;
    int t = threadIdx.x, ty = t >> 4, tx = t & 15;
    const float* Qb = Q + ((size_t)bh * SEQ + qt * 64) * DHD;
    for (int i = t; i < 64 * 16; i += 256) {
        int r = i >> 4, c = (i & 15) << 2;
        float4 v = *(const float4*)(Qb + r * DHD + c);
        Qs[r*65+c] = v.x; Qs[r*65+c+1] = v.y; Qs[r*65+c+2] = v.z; Qs[r*65+c+3] = v.w;
    }
    if (t < 64) { rowM[t] = -1e30f; rowL[t] = 0.f; }
    float acc[4][4] = {};
    __syncthreads();
    const float* Kb = K + (size_t)bh * SEQ * DHD;
    const float* Vb = V + (size_t)bh * SEQ * DHD;
    for (int kt = 0; kt <= qt; kt++) {
        for (int i = t; i < 64 * 16; i += 256) {
            int r = i >> 4, c = (i & 15) << 2;
            float4 kv = *(const float4*)(Kb + (size_t)(kt * 64 + r) * DHD + c);
            Ks[r*65+c] = kv.x; Ks[r*65+c+1] = kv.y; Ks[r*65+c+2] = kv.z; Ks[r*65+c+3] = kv.w;
            float4 vv = *(const float4*)(Vb + (size_t)(kt * 64 + r) * DHD + c);
            *(float4*)(Vs + r * 64 + c) = vv;
        }
        __syncthreads();
        float sc[4][4] = {};
#pragma unroll 8
        for (int d = 0; d < DHD; d++) {
            float a[4], bb[4];
#pragma unroll
            for (int i = 0; i < 4; i++) a[i] = Qs[(ty * 4 + i) * 65 + d];
#pragma unroll
            for (int j = 0; j < 4; j++) bb[j] = Ks[(tx * 4 + j) * 65 + d];
#pragma unroll
            for (int i = 0; i < 4; i++)
#pragma unroll
                for (int j = 0; j < 4; j++)
                    sc[i][j] = fmaf(a[i], bb[j], sc[i][j]);
        }
#pragma unroll
        for (int i = 0; i < 4; i++)
#pragma unroll
            for (int j = 0; j < 4; j++)
                Ss[(ty * 4 + i) * 65 + tx * 4 + j] = sc[i][j] * 0.125f;
        __syncthreads();
        if (t < 64) {
            int r = t;
            int lim = (kt == qt) ? (r + 1) : 64;
            float m = rowM[r];
            float mt = -1e30f;
            for (int c = 0; c < lim; c++) mt = fmaxf(mt, Ss[r * 65 + c]);
            float mn = fmaxf(m, mt);
            float f = expf(m - mn);
            float l = rowL[r] * f;
            for (int c = 0; c < 64; c++) {
                float p = (c < lim) ? expf(Ss[r * 65 + c] - mn) : 0.f;
                Ss[r * 65 + c] = p;
                l += p;
            }
            rowM[r] = mn; rowL[r] = l; rowF[r] = f;
        }
        __syncthreads();
        float fr[4];
#pragma unroll
        for (int i = 0; i < 4; i++) fr[i] = rowF[ty * 4 + i];
#pragma unroll
        for (int i = 0; i < 4; i++)
#pragma unroll
            for (int j = 0; j < 4; j++) acc[i][j] *= fr[i];
#pragma unroll 8
        for (int kk = 0; kk < 64; kk++) {
            float p[4], vv[4];
#pragma unroll
            for (int i = 0; i < 4; i++) p[i] = Ss[(ty * 4 + i) * 65 + kk];
#pragma unroll
            for (int j = 0; j < 4; j++) vv[j] = Vs[kk * 64 + tx * 4 + j];
#pragma unroll
            for (int i = 0; i < 4; i++)
#pragma unroll
                for (int j = 0; j < 4; j++)
                    acc[i][j] = fmaf(p[i], vv[j], acc[i][j]);
        }
        __syncthreads();
    }
    int b = bh >> 3, h = bh & 7;
#pragma unroll
    for (int i = 0; i < 4; i++) {
        int r = ty * 4 + i;
        float il = 1.0f / rowL[r];
        size_t base = ((size_t)b * SEQ + qt * 64 + r) * DIM + h * DHD;   // (B,S,D) layout
#pragma unroll
        for (int j = 0; j < 4; j++)
            O[base + tx * 4 + j] = acc[i][j] * il;
    }
}

// ---------------- head: logits -> sigmoid probs (one warp per row) ----------------
__global__ void head_kernel(const float* __restrict__ X, const float* __restrict__ hw,
                            const float* __restrict__ hb, float* __restrict__ probs) {
    int row = blockIdx.x * 8 + (threadIdx.x >> 5);
    int lane = threadIdx.x & 31;
    const float* xr = X + (size_t)row * DIM;
    float s = 0.f;
    for (int i = lane; i < DIM; i += 32) s = fmaf(xr[i], hw[i], s);
#pragma unroll
    for (int o = 16; o; o >>= 1) s += __shfl_xor_sync(0xffffffffu, s, o);
    if (lane == 0) {
        float logit = s + hb[0];
        probs[row] = 1.0f / (1.0f + expf(-logit));
    }
}

// ---------------- chunking: sequential per batch row ----------------
__global__ void chunk_kernel(const float* __restrict__ probs, int* __restrict__ ids,
                             int* __restrict__ nch, float* __restrict__ psum) {
    int b = blockIdx.x, t = threadIdx.x;
    __shared__ int flags[SEQ];
    __shared__ float red[256];
    const float* pr = probs + (size_t)b * SEQ;
    float s = 0.f; int any = 0;
    for (int i = t; i < SEQ; i += 256) {
        float p = pr[i];
        int f = (p > 0.5f) ? 1 : 0;
        flags[i] = f; s += p; any |= f;
    }
    red[t] = s;
    __syncthreads();
#pragma unroll
    for (int o = 128; o > 0; o >>= 1) {
        if (t < o) red[t] += red[t + o];
        __syncthreads();
    }
    int anyflag = __syncthreads_or(any);
    if (t == 0) {
        psum[b] = red[0];
        int cur_end = 0, cid = -1;
        for (int tt = 0; tt < SEQ; tt++) {
            if (tt == cur_end) {
                int cap = tt + 16; if (cap > SEQ) cap = SEQ;         // MAX_CL
                int e = cap;
                for (int ss = tt + 1; ss <= cap; ss++) {
                    int he = anyflag ? flags[ss - 1] : (ss == SEQ - 1);
                    if (he) { e = ss; break; }
                }
                if (e - tt < 3) { e = tt + 3; if (e > SEQ) e = SEQ; } // MIN_CL
                cur_end = e; cid++;
            }
            ids[b * SEQ + tt] = cid;
        }
        nch[b] = cid + 1;
    }
}

// ---------------- mask: out[b,i,j] = (ids[b,i]==ids[b,j]) ----------------
// OFF_MASK is odd -> scalar stores (no vector alignment)
__global__ void mask_kernel(const int* __restrict__ ids, float* __restrict__ out) {
    int i4 = blockIdx.x * 256 + threadIdx.x;        // 4,194,304 total
    int j = (i4 & 511) << 2;
    int rowIdx = i4 >> 9;                           // b*SEQ + i
    int b = rowIdx >> 11;
    int idi = ids[rowIdx];
    const int* idr = ids + b * SEQ;
    size_t base = ((size_t)rowIdx << 11) + j;
    out[base + 0] = (idi == idr[j + 0]) ? 1.f : 0.f;
    out[base + 1] = (idi == idr[j + 1]) ? 1.f : 0.f;
    out[base + 2] = (idi == idr[j + 2]) ? 1.f : 0.f;
    out[base + 3] = (idi == idr[j + 3]) ? 1.f : 0.f;
}

__global__ void scalars_kernel(const int* __restrict__ nch, const float* __restrict__ psum,
                               float* __restrict__ out_acl, float* __restrict__ out_cll) {
    float a = 0.f, c = 0.f;
    for (int b = 0; b < NUM_B; b++) {
        a += (float)SEQ / (float)nch[b];
        c += psum[b];
    }
    *out_acl = a * 0.25f;
    *out_cll = c * 0.25f;
}

__global__ void xids_kernel(const int* __restrict__ xids, float* __restrict__ out) {
    int i = blockIdx.x * 256 + threadIdx.x;
    out[i] = (float)xids[i];
}

// ---------------- launch ----------------
extern "C" void kernel_launch(void* const* d_in, const int* in_sizes, int n_in,
                              void* d_out, int out_size) {
    const float* x    = (const float*)d_in[0];
    const int*   xids = (const int*)  d_in[1];
    const float* ln1  = (const float*)d_in[2];
    const float* Wq   = (const float*)d_in[3];
    const float* Wk   = (const float*)d_in[4];
    const float* Wv   = (const float*)d_in[5];
    const float* Wo   = (const float*)d_in[6];
    const float* ln2  = (const float*)d_in[7];
    const float* W1   = (const float*)d_in[8];
    const float* W2   = (const float*)d_in[9];
    const float* hw   = (const float*)d_in[10];
    const float* hb   = (const float*)d_in[11];
    float* out = (float*)d_out;

    float *X, *Hn, *Ql, *Kl, *Vl, *Qr, *Kr, *Vr, *O, *G, *probs, *psum;
    int *ids, *nch;
    cudaGetSymbolAddress((void**)&X,  g_X);
    cudaGetSymbolAddress((void**)&Hn, g_Hn);
    cudaGetSymbolAddress((void**)&Ql, g_Ql);
    cudaGetSymbolAddress((void**)&Kl, g_Kl);
    cudaGetSymbolAddress((void**)&Vl, g_Vl);
    cudaGetSymbolAddress((void**)&Qr, g_Qr);
    cudaGetSymbolAddress((void**)&Kr, g_Kr);
    cudaGetSymbolAddress((void**)&Vr, g_Vr);
    cudaGetSymbolAddress((void**)&O,  g_O);
    cudaGetSymbolAddress((void**)&G,  g_G);
    cudaGetSymbolAddress((void**)&probs, g_probs);
    cudaGetSymbolAddress((void**)&psum,  g_psum);
    cudaGetSymbolAddress((void**)&ids, g_ids);
    cudaGetSymbolAddress((void**)&nch, g_nch);

    cudaFuncSetAttribute(attention_kernel, cudaFuncAttributeMaxDynamicSharedMemorySize, ATT_SMEM);

    cudaMemcpyAsync(X, x, sizeof(float) * (size_t)ROWS * DIM, cudaMemcpyDeviceToDevice, 0);

    dim3 g512(DIM / 64, ROWS / 64);   // (8, 128)
    dim3 gff (FF  / 64, ROWS / 64);   // (32, 128)

    for (int l = 0; l < NLAYER; l++) {
        const float* wq = Wq + (size_t)l * DIM * DIM;
        const float* wk = Wk + (size_t)l * DIM * DIM;
        const float* wv = Wv + (size_t)l * DIM * DIM;
        const float* wo = Wo + (size_t)l * DIM * DIM;
        const float* w1 = W1 + (size_t)l * DIM * FF;
        const float* w2 = W2 + (size_t)l * FF * DIM;

        rmsnorm_kernel<<<ROWS, 256>>>(X, ln1 + l * DIM, Hn);
        sgemm_kernel<0><<<g512, 256>>>(Hn, wq, nullptr, Ql, ROWS, DIM, DIM);
        sgemm_kernel<0><<<g512, 256>>>(Hn, wk, nullptr, Kl, ROWS, DIM, DIM);
        sgemm_kernel<0><<<g512, 256>>>(Hn, wv, nullptr, Vl, ROWS, DIM, DIM);
        rope_kernel  <<<ROWS, 256>>>(Ql, Qr);
        rope_kernel  <<<ROWS, 256>>>(Kl, Kr);
        vtrans_kernel<<<ROWS, 256>>>(Vl, Vr);
        attention_kernel<<<dim3(SEQ / 64, NUM_B * NH), 256, ATT_SMEM>>>(Qr, Kr, Vr, O);
        sgemm_kernel<1><<<g512, 256>>>(O, wo, X, X, ROWS, DIM, DIM);      // X += O @ Wo
        rmsnorm_kernel<<<ROWS, 256>>>(X, ln2 + l * DIM, Hn);
        sgemm_kernel<2><<<gff, 256>>>(Hn, w1, nullptr, G, ROWS, FF, DIM); // gelu
        sgemm_kernel<1><<<g512, 256>>>(G, w2, X, X, ROWS, DIM, FF);       // X += G @ W2
    }

    head_kernel <<<ROWS / 8, 256>>>(X, hw, hb, probs);
    chunk_kernel<<<NUM_B, 256>>>(probs, ids, nch, psum);
    mask_kernel <<<(N_MASK / 4) / 256, 256>>>(ids, out + OFF_MASK);
    scalars_kernel<<<1, 1>>>(nch, psum, out + OFF_ACL, out + OFF_CLL);
    xids_kernel <<<ROWS / 256, 256>>>(xids, out + OFF_IDS);
    cudaMemcpyAsync(out + OFF_XT, X, sizeof(float) * (size_t)ROWS * DIM, cudaMemcpyDeviceToDevice, 0);
}

// round 2
// speedup vs baseline: 1.7999x; 1.7999x over previous
#include <cuda_runtime.h>
#include <math.h>
#include <stdint.h>
#include <stddef.h>

// ---------------- problem constants ----------------
#define NUM_B 4
#define SEQ   2048
#define DIM   512
#define NH    8
#define DHD   64
#define FF    2048
#define ROWS  (NUM_B*SEQ)          // 8192
#define NLAYER 2

// output layout (float32, concatenated in reference return order)
#define OFF_XT   0
#define N_XT     (ROWS*DIM)                 // 4194304
#define OFF_IDS  (OFF_XT + N_XT)            // 4194304
#define N_IDS    (ROWS)                     // 8192
#define OFF_ACL  (OFF_IDS + N_IDS)          // 4202496
#define OFF_MASK (OFF_ACL + 1)              // 4202497 (odd -> scalar stores only)
#define N_MASK   (NUM_B*SEQ*SEQ)            // 16777216
#define OFF_CLL  (OFF_MASK + N_MASK)        // 20979713

// ---------------- scratch (device globals; no allocation allowed) ----------------
__device__ float g_X [ROWS*DIM];
__device__ float g_Hn[ROWS*DIM];
__device__ float g_Ql[ROWS*DIM];
__device__ float g_Kl[ROWS*DIM];
__device__ float g_Vl[ROWS*DIM];
__device__ float g_Qr[ROWS*DIM];
__device__ float g_Kr[ROWS*DIM];
__device__ float g_Vr[ROWS*DIM];
__device__ float g_O [ROWS*DIM];
__device__ float g_G [ROWS*FF];
__device__ float g_probs[ROWS];
__device__ int   g_ids[ROWS];
__device__ int   g_nch[NUM_B];
__device__ float g_psum[NUM_B];
__device__ float g_rc[SEQ*32];
__device__ float g_rs[SEQ*32];

// ---------------- rope table (computed once per launch; 65536 angles) ----------------
__global__ void rope_table_kernel(float* __restrict__ ct, float* __restrict__ st) {
    int i = threadIdx.x;            // 0..31
    int s = blockIdx.x;             // 0..2047
    double inv = pow(10000.0, -(double)i / 32.0);
    double ang = (double)s * inv;
    double sn, cs;
    sincos(ang, &sn, &cs);
    ct[s * 32 + i] = (float)cs;
    st[s * 32 + i] = (float)sn;
}

// ---------------- rmsnorm: one block per row (D=512, 256 threads) ----------------
__global__ void rmsnorm_kernel(const float* __restrict__ x, const float* __restrict__ w,
                               float* __restrict__ out) {
    int row = blockIdx.x;
    int t = threadIdx.x;
    const float* xr = x + (size_t)row * DIM;
    float v0 = xr[t], v1 = xr[t + 256];
    __shared__ float red[256];
    red[t] = v0 * v0 + v1 * v1;
    __syncthreads();
#pragma unroll
    for (int o = 128; o > 0; o >>= 1) {
        if (t < o) red[t] += red[t + o];
        __syncthreads();
    }
    float inv = rsqrtf(red[0] * (1.0f / (float)DIM) + 1e-6f);
    float* orow = out + (size_t)row * DIM;
    orow[t]       = v0 * inv * w[t];
    orow[t + 256] = v1 * inv * w[t + 256];
}

// ---------------- SGEMM: C[M,N] = A[M,K] @ B[K,N] (+epilogue) ----------------
// 128x128 tile, BK=16, 256 threads, 8x8 microtile, float4 smem reads,
// register prefetch of next global tile. M%128==0, N%128==0, K%16==0.
// EPI: 0 none, 1 add Cin (residual; Cin may alias C), 2 exact gelu
template<int EPI>
__global__ __launch_bounds__(256, 2)
void sgemm_kernel(const float* __restrict__ A, const float* __restrict__ B,
                  const float* Cin, float* C, int M, int N, int K) {
    __shared__ float As[16][132];   // [k][m], m padded
    __shared__ float Bs[16][132];   // [k][n], n padded
    int bm = blockIdx.y * 128, bn = blockIdx.x * 128;
    int t = threadIdx.x;
    int ty = t >> 4, tx = t & 15;
    int ar = t >> 2;                // 0..63
    int ak = (t & 3) << 2;          // 0,4,8,12
    int bk = t >> 5;                // 0..7
    int bnn = (t & 31) << 2;        // 0..124

    const float* Ap0 = A + (size_t)(bm + ar) * K + ak;
    const float* Ap1 = Ap0 + (size_t)64 * K;
    const float* Bp0 = B + (size_t)bk * N + bn + bnn;
    const float* Bp1 = Bp0 + (size_t)8 * N;

    float4 pa0 = *(const float4*)Ap0;
    float4 pa1 = *(const float4*)Ap1;
    float4 pb0 = *(const float4*)Bp0;
    float4 pb1 = *(const float4*)Bp1;

    float acc[8][8] = {};
    int k0 = 0;
    while (true) {
        As[ak + 0][ar] = pa0.x; As[ak + 1][ar] = pa0.y;
        As[ak + 2][ar] = pa0.z; As[ak + 3][ar] = pa0.w;
        As[ak + 0][64 + ar] = pa1.x; As[ak + 1][64 + ar] = pa1.y;
        As[ak + 2][64 + ar] = pa1.z; As[ak + 3][64 + ar] = pa1.w;
        *(float4*)&Bs[bk][bnn]     = pb0;
        *(float4*)&Bs[bk + 8][bnn] = pb1;
        __syncthreads();
        k0 += 16;
        bool more = (k0 < K);
        if (more) {
            pa0 = *(const float4*)(Ap0 + k0);
            pa1 = *(const float4*)(Ap1 + k0);
            pb0 = *(const float4*)(Bp0 + (size_t)k0 * N);
            pb1 = *(const float4*)(Bp1 + (size_t)k0 * N);
        }
#pragma unroll
        for (int kk = 0; kk < 16; kk++) {
            float4 a0 = *(const float4*)&As[kk][ty * 4];
            float4 a1 = *(const float4*)&As[kk][64 + ty * 4];
            float4 b0 = *(const float4*)&Bs[kk][tx * 4];
            float4 b1 = *(const float4*)&Bs[kk][64 + tx * 4];
            float a[8] = {a0.x, a0.y, a0.z, a0.w, a1.x, a1.y, a1.z, a1.w};
            float b[8] = {b0.x, b0.y, b0.z, b0.w, b1.x, b1.y, b1.z, b1.w};
#pragma unroll
            for (int i = 0; i < 8; i++)
#pragma unroll
                for (int j = 0; j < 8; j++)
                    acc[i][j] = fmaf(a[i], b[j], acc[i][j]);
        }
        if (!more) break;
        __syncthreads();
    }
#pragma unroll
    for (int ih = 0; ih < 2; ih++) {
#pragma unroll
        for (int i = 0; i < 4; i++) {
            int row = bm + ih * 64 + ty * 4 + i;
#pragma unroll
            for (int jh = 0; jh < 2; jh++) {
                int col = bn + jh * 64 + tx * 4;
                float4 v;
                v.x = acc[ih * 4 + i][jh * 4 + 0];
                v.y = acc[ih * 4 + i][jh * 4 + 1];
                v.z = acc[ih * 4 + i][jh * 4 + 2];
                v.w = acc[ih * 4 + i][jh * 4 + 3];
                if (EPI == 1) {
                    float4 c = *(const float4*)(Cin + (size_t)row * N + col);
                    v.x += c.x; v.y += c.y; v.z += c.z; v.w += c.w;
                }
                if (EPI == 2) {
                    v.x = 0.5f * v.x * (1.0f + erff(v.x * 0.70710678118654752f));
                    v.y = 0.5f * v.y * (1.0f + erff(v.y * 0.70710678118654752f));
                    v.z = 0.5f * v.z * (1.0f + erff(v.z * 0.70710678118654752f));
                    v.w = 0.5f * v.w * (1.0f + erff(v.w * 0.70710678118654752f));
                }
                *(float4*)(C + (size_t)row * N + col) = v;
            }
        }
    }
}

// ---------------- rope (table-driven) + head-transpose: (B,S,H*Dh) -> (B,H,S,Dh) ----
__global__ void rope_kernel(const float* __restrict__ lin, float* __restrict__ out,
                            const float* __restrict__ ct, const float* __restrict__ st) {
    int bs = blockIdx.x;              // b*SEQ + s
    int s = bs & (SEQ - 1);
    int b = bs >> 11;
    int h = threadIdx.x >> 5;
    int i = threadIdx.x & 31;
    const float* src = lin + (size_t)bs * DIM + h * DHD;
    float t1 = src[i], t2 = src[i + 32];
    float c  = ct[s * 32 + i];
    float si = st[s * 32 + i];
    float* dst = out + (((size_t)(b * NH + h)) * SEQ + s) * DHD;
    dst[i]      = t1 * c - t2 * si;
    dst[i + 32] = t1 * si + t2 * c;
}

__global__ void vtrans_kernel(const float* __restrict__ lin, float* __restrict__ out) {
    int bs = blockIdx.x;
    int s = bs & (SEQ - 1);
    int b = bs >> 11;
    int t = threadIdx.x;
    for (int e = t; e < DIM; e += 256) {
        int h = e >> 6, d = e & 63;
        out[(((size_t)(b * NH + h)) * SEQ + s) * DHD + d] = lin[(size_t)bs * DIM + e];
    }
}

// ---------------- flash attention: 64 q-rows/CTA, causal, online softmax ----------------
// Q,K staged transposed [d][n] for vector LDS in QK; parallel softmax (4 lanes/row).
#define ATT_FLOATS (3*64*68 + 64*64 + 3*64)
#define ATT_SMEM   (ATT_FLOATS * 4)     // 69376 bytes

__global__ __launch_bounds__(256)
void attention_kernel(const float* __restrict__ Q, const float* __restrict__ K,
                      const float* __restrict__ V, float* __restrict__ O) {
    extern __shared__ float sm[];
    float* Qst = sm;                    // [d][r]  64 x 68
    float* Kst = Qst + 64 * 68;         // [d][n]  64 x 68
    float* Ss  = Kst + 64 * 68;         // [r][c]  64 x 68
    float* Vs  = Ss  + 64 * 68;         // [k][n]  64 x 64
    float* rowM = Vs + 64 * 64;
    float* rowL = rowM + 64;
    float* rowF = rowL + 64;
    int bh = blockIdx.y;
    int qt = blockIdx.x;
    int t = threadIdx.x, ty = t >> 4, tx = t & 15;

    const float* Qb = Q + ((size_t)bh * SEQ + qt * 64) * DHD;
    for (int i = t; i < 64 * 16; i += 256) {
        int r = i >> 4, c = (i & 15) << 2;
        float4 v = *(const float4*)(Qb + r * DHD + c);
        Qst[(c + 0) * 68 + r] = v.x; Qst[(c + 1) * 68 + r] = v.y;
        Qst[(c + 2) * 68 + r] = v.z; Qst[(c + 3) * 68 + r] = v.w;
    }
    if (t < 64) { rowM[t] = -1e30f; rowL[t] = 0.f; }
    float acc[4][4] = {};
    __syncthreads();

    const float* Kb = K + (size_t)bh * SEQ * DHD;
    const float* Vb = V + (size_t)bh * SEQ * DHD;
    for (int kt = 0; kt <= qt; kt++) {
        for (int i = t; i < 64 * 16; i += 256) {
            int r = i >> 4, c = (i & 15) << 2;
            float4 kv = *(const float4*)(Kb + (size_t)(kt * 64 + r) * DHD + c);
            Kst[(c + 0) * 68 + r] = kv.x; Kst[(c + 1) * 68 + r] = kv.y;
            Kst[(c + 2) * 68 + r] = kv.z; Kst[(c + 3) * 68 + r] = kv.w;
            float4 vv = *(const float4*)(Vb + (size_t)(kt * 64 + r) * DHD + c);
            *(float4*)(Vs + r * 64 + c) = vv;
        }
        __syncthreads();
        // scores = Q @ K^T (rows ty*4.., cols tx*4..)
        float sc[4][4] = {};
#pragma unroll 8
        for (int d = 0; d < DHD; d++) {
            float4 a = *(const float4*)&Qst[d * 68 + ty * 4];
            float4 b = *(const float4*)&Kst[d * 68 + tx * 4];
            float ar[4] = {a.x, a.y, a.z, a.w};
            float br[4] = {b.x, b.y, b.z, b.w};
#pragma unroll
            for (int i = 0; i < 4; i++)
#pragma unroll
                for (int j = 0; j < 4; j++)
                    sc[i][j] = fmaf(ar[i], br[j], sc[i][j]);
        }
#pragma unroll
        for (int i = 0; i < 4; i++) {
            float4 v;
            v.x = sc[i][0] * 0.125f; v.y = sc[i][1] * 0.125f;
            v.z = sc[i][2] * 0.125f; v.w = sc[i][3] * 0.125f;
            *(float4*)&Ss[(ty * 4 + i) * 68 + tx * 4] = v;
        }
        __syncthreads();
        // parallel online softmax: 4 lanes per row, 16 cols each
        {
            int r = t >> 2, q = t & 3;
            int lim = (kt == qt) ? (r + 1) : 64;
            int c0 = q * 16;
            float m = -1e30f;
#pragma unroll
            for (int c = 0; c < 16; c++) {
                int cc = c0 + c;
                float v = Ss[r * 68 + cc];
                m = fmaxf(m, (cc < lim) ? v : -1e30f);
            }
            m = fmaxf(m, __shfl_xor_sync(0xffffffffu, m, 1));
            m = fmaxf(m, __shfl_xor_sync(0xffffffffu, m, 2));
            float mOld = rowM[r];
            float mn = fmaxf(mOld, m);
            float s = 0.f;
#pragma unroll
            for (int c = 0; c < 16; c++) {
                int cc = c0 + c;
                float p = (cc < lim) ? __expf(Ss[r * 68 + cc] - mn) : 0.f;
                Ss[r * 68 + cc] = p;
                s += p;
            }
            s += __shfl_xor_sync(0xffffffffu, s, 1);
            s += __shfl_xor_sync(0xffffffffu, s, 2);
            if (q == 0) {
                float f = __expf(mOld - mn);
                rowF[r] = f;
                rowL[r] = rowL[r] * f + s;
                rowM[r] = mn;
            }
        }
        __syncthreads();
        float fr[4];
#pragma unroll
        for (int i = 0; i < 4; i++) fr[i] = rowF[ty * 4 + i];
#pragma unroll
        for (int i = 0; i < 4; i++)
#pragma unroll
            for (int j = 0; j < 4; j++) acc[i][j] *= fr[i];
#pragma unroll 8
        for (int kk = 0; kk < 64; kk++) {
            float p[4];
#pragma unroll
            for (int i = 0; i < 4; i++) p[i] = Ss[(ty * 4 + i) * 68 + kk];
            float4 v = *(const float4*)&Vs[kk * 64 + tx * 4];
            float vr[4] = {v.x, v.y, v.z, v.w};
#pragma unroll
            for (int i = 0; i < 4; i++)
#pragma unroll
                for (int j = 0; j < 4; j++)
                    acc[i][j] = fmaf(p[i], vr[j], acc[i][j]);
        }
        __syncthreads();
    }
    int b = bh >> 3, h = bh & 7;
#pragma unroll
    for (int i = 0; i < 4; i++) {
        int r = ty * 4 + i;
        float il = 1.0f / rowL[r];
        size_t base = ((size_t)b * SEQ + qt * 64 + r) * DIM + h * DHD;   // (B,S,D) layout
#pragma unroll
        for (int j = 0; j < 4; j++)
            O[base + tx * 4 + j] = acc[i][j] * il;
    }
}

// ---------------- head: logits -> sigmoid probs (one warp per row) ----------------
__global__ void head_kernel(const float* __restrict__ X, const float* __restrict__ hw,
                            const float* __restrict__ hb, float* __restrict__ probs) {
    int row = blockIdx.x * 8 + (threadIdx.x >> 5);
    int lane = threadIdx.x & 31;
    const float* xr = X + (size_t)row * DIM;
    float s = 0.f;
    for (int i = lane; i < DIM; i += 32) s = fmaf(xr[i], hw[i], s);
#pragma unroll
    for (int o = 16; o; o >>= 1) s += __shfl_xor_sync(0xffffffffu, s, o);
    if (lane == 0) {
        float logit = s + hb[0];
        probs[row] = 1.0f / (1.0f + expf(-logit));
    }
}

// ---------------- chunking: sequential per batch row ----------------
__global__ void chunk_kernel(const float* __restrict__ probs, int* __restrict__ ids,
                             int* __restrict__ nch, float* __restrict__ psum) {
    int b = blockIdx.x, t = threadIdx.x;
    __shared__ int flags[SEQ];
    __shared__ float red[256];
    const float* pr = probs + (size_t)b * SEQ;
    float s = 0.f; int any = 0;
    for (int i = t; i < SEQ; i += 256) {
        float p = pr[i];
        int f = (p > 0.5f) ? 1 : 0;
        flags[i] = f; s += p; any |= f;
    }
    red[t] = s;
    __syncthreads();
#pragma unroll
    for (int o = 128; o > 0; o >>= 1) {
        if (t < o) red[t] += red[t + o];
        __syncthreads();
    }
    int anyflag = __syncthreads_or(any);
    if (t == 0) {
        psum[b] = red[0];
        int cur_end = 0, cid = -1;
        for (int tt = 0; tt < SEQ; tt++) {
            if (tt == cur_end) {
                int cap = tt + 16; if (cap > SEQ) cap = SEQ;         // MAX_CL
                int e = cap;
                for (int ss = tt + 1; ss <= cap; ss++) {
                    int he = anyflag ? flags[ss - 1] : (ss == SEQ - 1);
                    if (he) { e = ss; break; }
                }
                if (e - tt < 3) { e = tt + 3; if (e > SEQ) e = SEQ; } // MIN_CL
                cur_end = e; cid++;
            }
            ids[b * SEQ + tt] = cid;
        }
        nch[b] = cid + 1;
    }
}

// ---------------- mask: out[b,i,j] = (ids[b,i]==ids[b,j]) ----------------
__global__ void mask_kernel(const int* __restrict__ ids, float* __restrict__ out) {
    int i4 = blockIdx.x * 256 + threadIdx.x;        // 4,194,304 total
    int j = (i4 & 511) << 2;
    int rowIdx = i4 >> 9;                           // b*SEQ + i
    int b = rowIdx >> 11;
    int idi = ids[rowIdx];
    const int* idr = ids + b * SEQ;
    size_t base = ((size_t)rowIdx << 11) + j;
    out[base + 0] = (idi == idr[j + 0]) ? 1.f : 0.f;
    out[base + 1] = (idi == idr[j + 1]) ? 1.f : 0.f;
    out[base + 2] = (idi == idr[j + 2]) ? 1.f : 0.f;
    out[base + 3] = (idi == idr[j + 3]) ? 1.f : 0.f;
}

__global__ void scalars_kernel(const int* __restrict__ nch, const float* __restrict__ psum,
                               float* __restrict__ out_acl, float* __restrict__ out_cll) {
    float a = 0.f, c = 0.f;
    for (int b = 0; b < NUM_B; b++) {
        a += (float)SEQ / (float)nch[b];
        c += psum[b];
    }
    *out_acl = a * 0.25f;
    *out_cll = c * 0.25f;
}

__global__ void xids_kernel(const int* __restrict__ xids, float* __restrict__ out) {
    int i = blockIdx.x * 256 + threadIdx.x;
    out[i] = (float)xids[i];
}

// ---------------- launch ----------------
extern "C" void kernel_launch(void* const* d_in, const int* in_sizes, int n_in,
                              void* d_out, int out_size) {
    const float* x    = (const float*)d_in[0];
    const int*   xids = (const int*)  d_in[1];
    const float* ln1  = (const float*)d_in[2];
    const float* Wq   = (const float*)d_in[3];
    const float* Wk   = (const float*)d_in[4];
    const float* Wv   = (const float*)d_in[5];
    const float* Wo   = (const float*)d_in[6];
    const float* ln2  = (const float*)d_in[7];
    const float* W1   = (const float*)d_in[8];
    const float* W2   = (const float*)d_in[9];
    const float* hw   = (const float*)d_in[10];
    const float* hb   = (const float*)d_in[11];
    float* out = (float*)d_out;

    float *X, *Hn, *Ql, *Kl, *Vl, *Qr, *Kr, *Vr, *O, *G, *probs, *psum, *rc, *rs;
    int *ids, *nch;
    cudaGetSymbolAddress((void**)&X,  g_X);
    cudaGetSymbolAddress((void**)&Hn, g_Hn);
    cudaGetSymbolAddress((void**)&Ql, g_Ql);
    cudaGetSymbolAddress((void**)&Kl, g_Kl);
    cudaGetSymbolAddress((void**)&Vl, g_Vl);
    cudaGetSymbolAddress((void**)&Qr, g_Qr);
    cudaGetSymbolAddress((void**)&Kr, g_Kr);
    cudaGetSymbolAddress((void**)&Vr, g_Vr);
    cudaGetSymbolAddress((void**)&O,  g_O);
    cudaGetSymbolAddress((void**)&G,  g_G);
    cudaGetSymbolAddress((void**)&probs, g_probs);
    cudaGetSymbolAddress((void**)&psum,  g_psum);
    cudaGetSymbolAddress((void**)&ids, g_ids);
    cudaGetSymbolAddress((void**)&nch, g_nch);
    cudaGetSymbolAddress((void**)&rc, g_rc);
    cudaGetSymbolAddress((void**)&rs, g_rs);

    cudaFuncSetAttribute(attention_kernel, cudaFuncAttributeMaxDynamicSharedMemorySize, ATT_SMEM);

    rope_table_kernel<<<SEQ, 32>>>(rc, rs);
    cudaMemcpyAsync(X, x, sizeof(float) * (size_t)ROWS * DIM, cudaMemcpyDeviceToDevice, 0);

    dim3 g512(DIM / 128, ROWS / 128);   // (4, 64)
    dim3 gff (FF  / 128, ROWS / 128);   // (16, 64)

    for (int l = 0; l < NLAYER; l++) {
        const float* wq = Wq + (size_t)l * DIM * DIM;
        const float* wk = Wk + (size_t)l * DIM * DIM;
        const float* wv = Wv + (size_t)l * DIM * DIM;
        const float* wo = Wo + (size_t)l * DIM * DIM;
        const float* w1 = W1 + (size_t)l * DIM * FF;
        const float* w2 = W2 + (size_t)l * FF * DIM;

        rmsnorm_kernel<<<ROWS, 256>>>(X, ln1 + l * DIM, Hn);
        sgemm_kernel<0><<<g512, 256>>>(Hn, wq, nullptr, Ql, ROWS, DIM, DIM);
        sgemm_kernel<0><<<g512, 256>>>(Hn, wk, nullptr, Kl, ROWS, DIM, DIM);
        sgemm_kernel<0><<<g512, 256>>>(Hn, wv, nullptr, Vl, ROWS, DIM, DIM);
        rope_kernel  <<<ROWS, 256>>>(Ql, Qr, rc, rs);
        rope_kernel  <<<ROWS, 256>>>(Kl, Kr, rc, rs);
        vtrans_kernel<<<ROWS, 256>>>(Vl, Vr);
        attention_kernel<<<dim3(SEQ / 64, NUM_B * NH), 256, ATT_SMEM>>>(Qr, Kr, Vr, O);
        sgemm_kernel<1><<<g512, 256>>>(O, wo, X, X, ROWS, DIM, DIM);      // X += O @ Wo
        rmsnorm_kernel<<<ROWS, 256>>>(X, ln2 + l * DIM, Hn);
        sgemm_kernel<2><<<gff, 256>>>(Hn, w1, nullptr, G, ROWS, FF, DIM); // gelu
        sgemm_kernel<1><<<g512, 256>>>(G, w2, X, X, ROWS, DIM, FF);       // X += G @ W2
    }

    head_kernel <<<ROWS / 8, 256>>>(X, hw, hb, probs);
    chunk_kernel<<<NUM_B, 256>>>(probs, ids, nch, psum);
    mask_kernel <<<(N_MASK / 4) / 256, 256>>>(ids, out + OFF_MASK);
    scalars_kernel<<<1, 1>>>(nch, psum, out + OFF_ACL, out + OFF_CLL);
    xids_kernel <<<ROWS / 256, 256>>>(xids, out + OFF_IDS);
    cudaMemcpyAsync(out + OFF_XT, X, sizeof(float) * (size_t)ROWS * DIM, cudaMemcpyDeviceToDevice, 0);
}

// round 4
// speedup vs baseline: 2.4827x; 1.3793x over previous
#include <cuda_runtime.h>
#include <cuda_bf16.h>
#include <math.h>
#include <stdint.h>
#include <stddef.h>

// ---------------- problem constants ----------------
#define NUM_B 4
#define SEQ   2048
#define DIM   512
#define NH    8
#define DHD   64
#define FF    2048
#define ROWS  (NUM_B*SEQ)          // 8192
#define NLAYER 2

// output layout (float32, concatenated in reference return order)
#define OFF_XT   0
#define N_XT     (ROWS*DIM)                 // 4194304
#define OFF_IDS  (OFF_XT + N_XT)            // 4194304
#define N_IDS    (ROWS)                     // 8192
#define OFF_ACL  (OFF_IDS + N_IDS)          // 4202496
#define OFF_MASK (OFF_ACL + 1)              // 4202497 (odd -> scalar stores only)
#define N_MASK   (NUM_B*SEQ*SEQ)            // 16777216
#define OFF_CLL  (OFF_MASK + N_MASK)        // 20979713

// per-layer transposed-weight bf16 buffer layout (elements)
#define WT_Q   0
#define WT_K   (512*512)
#define WT_V   (2*512*512)
#define WT_O   (3*512*512)
#define WT_W1  (4*512*512)                  // [2048][512]
#define WT_W2  (4*512*512 + 2048*512)       // [512][2048]
#define WT_LAYER (4*512*512 + 2*2048*512)   // 3145728

// ---------------- scratch (device globals; no allocation allowed) ----------------
__device__ float g_X [ROWS*DIM];
__device__ float g_Ql[ROWS*DIM];
__device__ float g_Kl[ROWS*DIM];
__device__ float g_Vl[ROWS*DIM];
__device__ float g_Qr[ROWS*DIM];
__device__ float g_Kr[ROWS*DIM];
__device__ float g_Vr[ROWS*DIM];
__device__ __nv_bfloat16 g_Ahi[ROWS*DIM];
__device__ __nv_bfloat16 g_Alo[ROWS*DIM];
__device__ __nv_bfloat16 g_Ghi[ROWS*FF];
__device__ __nv_bfloat16 g_Glo[ROWS*FF];
__device__ __nv_bfloat16 g_WThi[NLAYER*WT_LAYER];
__device__ __nv_bfloat16 g_WTlo[NLAYER*WT_LAYER];
__device__ float g_probs[ROWS];
__device__ int   g_ids[ROWS];
__device__ int   g_nch[NUM_B];
__device__ float g_psum[NUM_B];
__device__ float g_rc[SEQ*32];
__device__ float g_rs[SEQ*32];

// ---------------- mma.sync helper (bf16 x bf16 -> fp32, m16n8k16) ----------------
__device__ __forceinline__ void mma16816(float* c, const uint32_t* a, const uint32_t* b) {
    asm volatile(
        "mma.sync.aligned.m16n8k16.row.col.f32.bf16.bf16.f32 "
        "{%0,%1,%2,%3}, {%4,%5,%6,%7}, {%8,%9}, {%0,%1,%2,%3};"
        : "+f"(c[0]), "+f"(c[1]), "+f"(c[2]), "+f"(c[3])
        : "r"(a[0]), "r"(a[1]), "r"(a[2]), "r"(a[3]), "r"(b[0]), "r"(b[1]));
}

// ---------------- HMMA GEMM: C[M,N] = (Ahi+Alo) @ (Bhi+Blo)^T ----------------
// A: [M][K] bf16 hi/lo (row-major K contiguous). B: [N][K] bf16 hi/lo (pre-transposed).
// CTA tile 128x128, BK=32, 256 threads (8 warps, 2x4 grid, 64x32 per warp).
// 3-term split precision: hi*hi + hi*lo + lo*hi.
// EPI: 0 = store fp32, 1 = residual add (Cin may alias C), 3 = gelu -> bf16 hi/lo split
#define SKP 40   // padded smem row stride (elements); 80B, 16B-multiple, conflict-free frags

template<int EPI>
__global__ __launch_bounds__(256)
void hmma_gemm_kernel(const __nv_bfloat16* __restrict__ Ahi, const __nv_bfloat16* __restrict__ Alo,
                      const __nv_bfloat16* __restrict__ Bhi, const __nv_bfloat16* __restrict__ Blo,
                      const float* __restrict__ Cin, float* __restrict__ C,
                      __nv_bfloat16* __restrict__ Ghi, __nv_bfloat16* __restrict__ Glo,
                      int M, int N, int K) {
    __shared__ __align__(16) __nv_bfloat16 sAh[128 * SKP];
    __shared__ __align__(16) __nv_bfloat16 sAl[128 * SKP];
    __shared__ __align__(16) __nv_bfloat16 sBh[128 * SKP];
    __shared__ __align__(16) __nv_bfloat16 sBl[128 * SKP];

    const int tid = threadIdx.x;
    const int bm = blockIdx.y * 128, bn = blockIdx.x * 128;
    const int w = tid >> 5, lane = tid & 31;
    const int wm = (w & 1) * 64;        // warp m offset in tile
    const int wn = (w >> 1) * 32;       // warp n offset in tile
    const int g = lane >> 2;            // group id 0..7
    const int tg = lane & 3;            // thread-in-group

    float acc[4][4][4] = {};            // [mt][nt][c0..c3]

    const int nchunk = K >> 5;          // BK=32
    for (int kc = 0; kc < nchunk; kc++) {
        // stage global -> smem (4 buffers)
        for (int idx = tid; idx < 512; idx += 256) {
            int r = idx >> 2;                 // 0..127
            int ko = (idx & 3) << 3;          // 0,8,16,24
            size_t ga = (size_t)(bm + r) * K + (size_t)kc * 32 + ko;
            size_t gb = (size_t)(bn + r) * K + (size_t)kc * 32 + ko;
            *(uint4*)&sAh[r * SKP + ko] = *(const uint4*)(Ahi + ga);
            *(uint4*)&sAl[r * SKP + ko] = *(const uint4*)(Alo + ga);
            *(uint4*)&sBh[r * SKP + ko] = *(const uint4*)(Bhi + gb);
            *(uint4*)&sBl[r * SKP + ko] = *(const uint4*)(Blo + gb);
        }
        __syncthreads();
#pragma unroll
        for (int ks = 0; ks < 2; ks++) {
            const int k0 = ks * 16;
            const int kk = k0 + tg * 2;
            // B fragments for this warp's 4 n-tiles (hi and lo)
            uint32_t bh[4][2], bl[4][2];
#pragma unroll
            for (int nt = 0; nt < 4; nt++) {
                int nr = wn + nt * 8 + g;
                bh[nt][0] = *(const uint32_t*)&sBh[nr * SKP + kk];
                bh[nt][1] = *(const uint32_t*)&sBh[nr * SKP + kk + 8];
                bl[nt][0] = *(const uint32_t*)&sBl[nr * SKP + kk];
                bl[nt][1] = *(const uint32_t*)&sBl[nr * SKP + kk + 8];
            }
#pragma unroll
            for (int mt = 0; mt < 4; mt++) {
                int r0 = wm + mt * 16 + g;
                int r1 = r0 + 8;
                uint32_t ah[4], al[4];
                ah[0] = *(const uint32_t*)&sAh[r0 * SKP + kk];
                ah[1] = *(const uint32_t*)&sAh[r1 * SKP + kk];
                ah[2] = *(const uint32_t*)&sAh[r0 * SKP + kk + 8];
                ah[3] = *(const uint32_t*)&sAh[r1 * SKP + kk + 8];
                al[0] = *(const uint32_t*)&sAl[r0 * SKP + kk];
                al[1] = *(const uint32_t*)&sAl[r1 * SKP + kk];
                al[2] = *(const uint32_t*)&sAl[r0 * SKP + kk + 8];
                al[3] = *(const uint32_t*)&sAl[r1 * SKP + kk + 8];
#pragma unroll
                for (int nt = 0; nt < 4; nt++) {
                    mma16816(acc[mt][nt], ah, bh[nt]);
                    mma16816(acc[mt][nt], ah, bl[nt]);
                    mma16816(acc[mt][nt], al, bh[nt]);
                }
            }
        }
        __syncthreads();
    }

    // epilogue: documented c-fragment mapping
    //   c0,c1 -> (row g, col tg*2 .. +1); c2,c3 -> (row g+8, same cols)
#pragma unroll
    for (int mt = 0; mt < 4; mt++) {
        int row0 = bm + wm + mt * 16 + g;
        int row1 = row0 + 8;
#pragma unroll
        for (int nt = 0; nt < 4; nt++) {
            int col = bn + wn + nt * 8 + tg * 2;
            float c0 = acc[mt][nt][0], c1 = acc[mt][nt][1];
            float c2 = acc[mt][nt][2], c3 = acc[mt][nt][3];
            if (EPI == 0 || EPI == 1) {
                if (EPI == 1) {
                    float2 r0 = *(const float2*)(Cin + (size_t)row0 * N + col);
                    float2 r1 = *(const float2*)(Cin + (size_t)row1 * N + col);
                    c0 += r0.x; c1 += r0.y; c2 += r1.x; c3 += r1.y;
                }
                float2 v0 = {c0, c1}, v1 = {c2, c3};
                *(float2*)(C + (size_t)row0 * N + col) = v0;
                *(float2*)(C + (size_t)row1 * N + col) = v1;
            } else {  // EPI 3: gelu -> bf16 hi/lo split
                float vv[4] = {c0, c1, c2, c3};
                __nv_bfloat16 h[4], l[4];
#pragma unroll
                for (int e = 0; e < 4; e++) {
                    float v = vv[e];
                    v = 0.5f * v * (1.0f + erff(v * 0.70710678118654752f));
                    h[e] = __float2bfloat16(v);
                    l[e] = __float2bfloat16(v - __bfloat162float(h[e]));
                }
                *(__nv_bfloat162*)(Ghi + (size_t)row0 * N + col) = {h[0], h[1]};
                *(__nv_bfloat162*)(Ghi + (size_t)row1 * N + col) = {h[2], h[3]};
                *(__nv_bfloat162*)(Glo + (size_t)row0 * N + col) = {l[0], l[1]};
                *(__nv_bfloat162*)(Glo + (size_t)row1 * N + col) = {l[2], l[3]};
            }
        }
    }
}

// ---------------- weight transpose + bf16 hi/lo split: W[K][N] -> T[N][K] ----------------
__global__ void wsplit_kernel(const float* __restrict__ W, __nv_bfloat16* __restrict__ Th,
                              __nv_bfloat16* __restrict__ Tl, int K, int N) {
    __shared__ float tile[32][33];
    int n0 = blockIdx.x * 32, k0 = blockIdx.y * 32;
    int tx = threadIdx.x & 31, ty = threadIdx.x >> 5;
#pragma unroll
    for (int i = 0; i < 32; i += 8)
        tile[ty + i][tx] = W[(size_t)(k0 + ty + i) * N + n0 + tx];
    __syncthreads();
#pragma unroll
    for (int i = 0; i < 32; i += 8) {
        float v = tile[tx][ty + i];
        __nv_bfloat16 h = __float2bfloat16(v);
        __nv_bfloat16 l = __float2bfloat16(v - __bfloat162float(h));
        size_t o = (size_t)(n0 + ty + i) * K + k0 + tx;
        Th[o] = h; Tl[o] = l;
    }
}

// ---------------- rope table (computed once per launch; 65536 angles) ----------------
__global__ void rope_table_kernel(float* __restrict__ ct, float* __restrict__ st) {
    int i = threadIdx.x;            // 0..31
    int s = blockIdx.x;             // 0..2047
    double inv = pow(10000.0, -(double)i / 32.0);
    double ang = (double)s * inv;
    double sn, cs;
    sincos(ang, &sn, &cs);
    ct[s * 32 + i] = (float)cs;
    st[s * 32 + i] = (float)sn;
}

// ---------------- rmsnorm + bf16 hi/lo split: one block per row ----------------
__global__ void rmsnorm_split_kernel(const float* __restrict__ x, const float* __restrict__ w,
                                     __nv_bfloat16* __restrict__ hi, __nv_bfloat16* __restrict__ lo) {
    int row = blockIdx.x;
    int t = threadIdx.x;
    const float* xr = x + (size_t)row * DIM;
    float v0 = xr[t], v1 = xr[t + 256];
    __shared__ float red[256];
    red[t] = v0 * v0 + v1 * v1;
    __syncthreads();
#pragma unroll
    for (int o = 128; o > 0; o >>= 1) {
        if (t < o) red[t] += red[t + o];
        __syncthreads();
    }
    float inv = rsqrtf(red[0] * (1.0f / (float)DIM) + 1e-6f);
    float y0 = v0 * inv * w[t];
    float y1 = v1 * inv * w[t + 256];
    __nv_bfloat16 h0 = __float2bfloat16(y0);
    __nv_bfloat16 h1 = __float2bfloat16(y1);
    size_t o0 = (size_t)row * DIM + t;
    hi[o0]       = h0;  lo[o0]       = __float2bfloat16(y0 - __bfloat162float(h0));
    hi[o0 + 256] = h1;  lo[o0 + 256] = __float2bfloat16(y1 - __bfloat162float(h1));
}

// ---------------- rope (table-driven) + head-transpose: (B,S,H*Dh) -> (B,H,S,Dh) ----
__global__ void rope_kernel(const float* __restrict__ lin, float* __restrict__ out,
                            const float* __restrict__ ct, const float* __restrict__ st) {
    int bs = blockIdx.x;              // b*SEQ + s
    int s = bs & (SEQ - 1);
    int b = bs >> 11;
    int h = threadIdx.x >> 5;
    int i = threadIdx.x & 31;
    const float* src = lin + (size_t)bs * DIM + h * DHD;
    float t1 = src[i], t2 = src[i + 32];
    float c  = ct[s * 32 + i];
    float si = st[s * 32 + i];
    float* dst = out + (((size_t)(b * NH + h)) * SEQ + s) * DHD;
    dst[i]      = t1 * c - t2 * si;
    dst[i + 32] = t1 * si + t2 * c;
}

__global__ void vtrans_kernel(const float* __restrict__ lin, float* __restrict__ out) {
    int bs = blockIdx.x;
    int s = bs & (SEQ - 1);
    int b = bs >> 11;
    int t = threadIdx.x;
    for (int e = t; e < DIM; e += 256) {
        int h = e >> 6, d = e & 63;
        out[(((size_t)(b * NH + h)) * SEQ + s) * DHD + d] = lin[(size_t)bs * DIM + e];
    }
}

// ---------------- flash attention: 64 q-rows/CTA, causal, online softmax ----------------
// outputs bf16 hi/lo split directly (consumed by Wo HMMA GEMM)
#define ATT_FLOATS (3*64*68 + 64*64 + 3*64)
#define ATT_SMEM   (ATT_FLOATS * 4)     // 69376 bytes

__global__ __launch_bounds__(256)
void attention_kernel(const float* __restrict__ Q, const float* __restrict__ K,
                      const float* __restrict__ V,
                      __nv_bfloat16* __restrict__ Ohi, __nv_bfloat16* __restrict__ Olo) {
    extern __shared__ float sm[];
    float* Qst = sm;                    // [d][r]  64 x 68
    float* Kst = Qst + 64 * 68;         // [d][n]  64 x 68
    float* Ss  = Kst + 64 * 68;         // [r][c]  64 x 68
    float* Vs  = Ss  + 64 * 68;         // [k][n]  64 x 64
    float* rowM = Vs + 64 * 64;
    float* rowL = rowM + 64;
    float* rowF = rowL + 64;
    int bh = blockIdx.y;
    int qt = blockIdx.x;
    int t = threadIdx.x, ty = t >> 4, tx = t & 15;

    const float* Qb = Q + ((size_t)bh * SEQ + qt * 64) * DHD;
    for (int i = t; i < 64 * 16; i += 256) {
        int r = i >> 4, c = (i & 15) << 2;
        float4 v = *(const float4*)(Qb + r * DHD + c);
        Qst[(c + 0) * 68 + r] = v.x; Qst[(c + 1) * 68 + r] = v.y;
        Qst[(c + 2) * 68 + r] = v.z; Qst[(c + 3) * 68 + r] = v.w;
    }
    if (t < 64) { rowM[t] = -1e30f; rowL[t] = 0.f; }
    float acc[4][4] = {};
    __syncthreads();

    const float* Kb = K + (size_t)bh * SEQ * DHD;
    const float* Vb = V + (size_t)bh * SEQ * DHD;
    for (int kt = 0; kt <= qt; kt++) {
        for (int i = t; i < 64 * 16; i += 256) {
            int r = i >> 4, c = (i & 15) << 2;
            float4 kv = *(const float4*)(Kb + (size_t)(kt * 64 + r) * DHD + c);
            Kst[(c + 0) * 68 + r] = kv.x; Kst[(c + 1) * 68 + r] = kv.y;
            Kst[(c + 2) * 68 + r] = kv.z; Kst[(c + 3) * 68 + r] = kv.w;
            float4 vv = *(const float4*)(Vb + (size_t)(kt * 64 + r) * DHD + c);
            *(float4*)(Vs + r * 64 + c) = vv;
        }
        __syncthreads();
        float sc[4][4] = {};
#pragma unroll 8
        for (int d = 0; d < DHD; d++) {
            float4 a = *(const float4*)&Qst[d * 68 + ty * 4];
            float4 b = *(const float4*)&Kst[d * 68 + tx * 4];
            float ar[4] = {a.x, a.y, a.z, a.w};
            float br[4] = {b.x, b.y, b.z, b.w};
#pragma unroll
            for (int i = 0; i < 4; i++)
#pragma unroll
                for (int j = 0; j < 4; j++)
                    sc[i][j] = fmaf(ar[i], br[j], sc[i][j]);
        }
#pragma unroll
        for (int i = 0; i < 4; i++) {
            float4 v;
            v.x = sc[i][0] * 0.125f; v.y = sc[i][1] * 0.125f;
            v.z = sc[i][2] * 0.125f; v.w = sc[i][3] * 0.125f;
            *(float4*)&Ss[(ty * 4 + i) * 68 + tx * 4] = v;
        }
        __syncthreads();
        {
            int r = t >> 2, q = t & 3;
            int lim = (kt == qt) ? (r + 1) : 64;
            int c0 = q * 16;
            float m = -1e30f;
#pragma unroll
            for (int c = 0; c < 16; c++) {
                int cc = c0 + c;
                float v = Ss[r * 68 + cc];
                m = fmaxf(m, (cc < lim) ? v : -1e30f);
            }
            m = fmaxf(m, __shfl_xor_sync(0xffffffffu, m, 1));
            m = fmaxf(m, __shfl_xor_sync(0xffffffffu, m, 2));
            float mOld = rowM[r];
            float mn = fmaxf(mOld, m);
            float s = 0.f;
#pragma unroll
            for (int c = 0; c < 16; c++) {
                int cc = c0 + c;
                float p = (cc < lim) ? __expf(Ss[r * 68 + cc] - mn) : 0.f;
                Ss[r * 68 + cc] = p;
                s += p;
            }
            s += __shfl_xor_sync(0xffffffffu, s, 1);
            s += __shfl_xor_sync(0xffffffffu, s, 2);
            if (q == 0) {
                float f = __expf(mOld - mn);
                rowF[r] = f;
                rowL[r] = rowL[r] * f + s;
                rowM[r] = mn;
            }
        }
        __syncthreads();
        float fr[4];
#pragma unroll
        for (int i = 0; i < 4; i++) fr[i] = rowF[ty * 4 + i];
#pragma unroll
        for (int i = 0; i < 4; i++)
#pragma unroll
            for (int j = 0; j < 4; j++) acc[i][j] *= fr[i];
#pragma unroll 8
        for (int kk = 0; kk < 64; kk++) {
            float p[4];
#pragma unroll
            for (int i = 0; i < 4; i++) p[i] = Ss[(ty * 4 + i) * 68 + kk];
            float4 v = *(const float4*)&Vs[kk * 64 + tx * 4];
            float vr[4] = {v.x, v.y, v.z, v.w};
#pragma unroll
            for (int i = 0; i < 4; i++)
#pragma unroll
                for (int j = 0; j < 4; j++)
                    acc[i][j] = fmaf(p[i], vr[j], acc[i][j]);
        }
        __syncthreads();
    }
    int b = bh >> 3, h = bh & 7;
#pragma unroll
    for (int i = 0; i < 4; i++) {
        int r = ty * 4 + i;
        float il = 1.0f / rowL[r];
        size_t base = ((size_t)b * SEQ + qt * 64 + r) * DIM + h * DHD;   // (B,S,D) layout
#pragma unroll
        for (int j = 0; j < 4; j++) {
            float v = acc[i][j] * il;
            __nv_bfloat16 hh = __float2bfloat16(v);
            Ohi[base + tx * 4 + j] = hh;
            Olo[base + tx * 4 + j] = __float2bfloat16(v - __bfloat162float(hh));
        }
    }
}

// ---------------- head: logits -> sigmoid probs (one warp per row) ----------------
__global__ void head_kernel(const float* __restrict__ X, const float* __restrict__ hw,
                            const float* __restrict__ hb, float* __restrict__ probs) {
    int row = blockIdx.x * 8 + (threadIdx.x >> 5);
    int lane = threadIdx.x & 31;
    const float* xr = X + (size_t)row * DIM;
    float s = 0.f;
    for (int i = lane; i < DIM; i += 32) s = fmaf(xr[i], hw[i], s);
#pragma unroll
    for (int o = 16; o; o >>= 1) s += __shfl_xor_sync(0xffffffffu, s, o);
    if (lane == 0) {
        float logit = s + hb[0];
        probs[row] = 1.0f / (1.0f + expf(-logit));
    }
}

// ---------------- chunking: sequential per batch row ----------------
__global__ void chunk_kernel(const float* __restrict__ probs, int* __restrict__ ids,
                             int* __restrict__ nch, float* __restrict__ psum) {
    int b = blockIdx.x, t = threadIdx.x;
    __shared__ int flags[SEQ];
    __shared__ float red[256];
    const float* pr = probs + (size_t)b * SEQ;
    float s = 0.f; int any = 0;
    for (int i = t; i < SEQ; i += 256) {
        float p = pr[i];
        int f = (p > 0.5f) ? 1 : 0;
        flags[i] = f; s += p; any |= f;
    }
    red[t] = s;
    __syncthreads();
#pragma unroll
    for (int o = 128; o > 0; o >>= 1) {
        if (t < o) red[t] += red[t + o];
        __syncthreads();
    }
    int anyflag = __syncthreads_or(any);
    if (t == 0) {
        psum[b] = red[0];
        int cur_end = 0, cid = -1;
        for (int tt = 0; tt < SEQ; tt++) {
            if (tt == cur_end) {
                int cap = tt + 16; if (cap > SEQ) cap = SEQ;         // MAX_CL
                int e = cap;
                for (int ss = tt + 1; ss <= cap; ss++) {
                    int he = anyflag ? flags[ss - 1] : (ss == SEQ - 1);
                    if (he) { e = ss; break; }
                }
                if (e - tt < 3) { e = tt + 3; if (e > SEQ) e = SEQ; } // MIN_CL
                cur_end = e; cid++;
            }
            ids[b * SEQ + tt] = cid;
        }
        nch[b] = cid + 1;
    }
}

// ---------------- mask: out[b,i,j] = (ids[b,i]==ids[b,j]) ----------------
__global__ void mask_kernel(const int* __restrict__ ids, float* __restrict__ out) {
    int i4 = blockIdx.x * 256 + threadIdx.x;        // 4,194,304 total
    int j = (i4 & 511) << 2;
    int rowIdx = i4 >> 9;                           // b*SEQ + i
    int b = rowIdx >> 11;
    int idi = ids[rowIdx];
    const int* idr = ids + b * SEQ;
    size_t base = ((size_t)rowIdx << 11) + j;
    out[base + 0] = (idi == idr[j + 0]) ? 1.f : 0.f;
    out[base + 1] = (idi == idr[j + 1]) ? 1.f : 0.f;
    out[base + 2] = (idi == idr[j + 2]) ? 1.f : 0.f;
    out[base + 3] = (idi == idr[j + 3]) ? 1.f : 0.f;
}

__global__ void scalars_kernel(const int* __restrict__ nch, const float* __restrict__ psum,
                               float* __restrict__ out_acl, float* __restrict__ out_cll) {
    float a = 0.f, c = 0.f;
    for (int b = 0; b < NUM_B; b++) {
        a += (float)SEQ / (float)nch[b];
        c += psum[b];
    }
    *out_acl = a * 0.25f;
    *out_cll = c * 0.25f;
}

__global__ void xids_kernel(const int* __restrict__ xids, float* __restrict__ out) {
    int i = blockIdx.x * 256 + threadIdx.x;
    out[i] = (float)xids[i];
}

// ---------------- launch ----------------
extern "C" void kernel_launch(void* const* d_in, const int* in_sizes, int n_in,
                              void* d_out, int out_size) {
    const float* x    = (const float*)d_in[0];
    const int*   xids = (const int*)  d_in[1];
    const float* ln1  = (const float*)d_in[2];
    const float* Wq   = (const float*)d_in[3];
    const float* Wk   = (const float*)d_in[4];
    const float* Wv   = (const float*)d_in[5];
    const float* Wo   = (const float*)d_in[6];
    const float* ln2  = (const float*)d_in[7];
    const float* W1   = (const float*)d_in[8];
    const float* W2   = (const float*)d_in[9];
    const float* hw   = (const float*)d_in[10];
    const float* hb   = (const float*)d_in[11];
    float* out = (float*)d_out;

    float *X, *Ql, *Kl, *Vl, *Qr, *Kr, *Vr, *probs, *psum, *rc, *rs;
    __nv_bfloat16 *Ahi, *Alo, *Ghi, *Glo, *WThi, *WTlo;
    int *ids, *nch;
    cudaGetSymbolAddress((void**)&X,  g_X);
    cudaGetSymbolAddress((void**)&Ql, g_Ql);
    cudaGetSymbolAddress((void**)&Kl, g_Kl);
    cudaGetSymbolAddress((void**)&Vl, g_Vl);
    cudaGetSymbolAddress((void**)&Qr, g_Qr);
    cudaGetSymbolAddress((void**)&Kr, g_Kr);
    cudaGetSymbolAddress((void**)&Vr, g_Vr);
    cudaGetSymbolAddress((void**)&Ahi, g_Ahi);
    cudaGetSymbolAddress((void**)&Alo, g_Alo);
    cudaGetSymbolAddress((void**)&Ghi, g_Ghi);
    cudaGetSymbolAddress((void**)&Glo, g_Glo);
    cudaGetSymbolAddress((void**)&WThi, g_WThi);
    cudaGetSymbolAddress((void**)&WTlo, g_WTlo);
    cudaGetSymbolAddress((void**)&probs, g_probs);
    cudaGetSymbolAddress((void**)&psum,  g_psum);
    cudaGetSymbolAddress((void**)&ids, g_ids);
    cudaGetSymbolAddress((void**)&nch, g_nch);
    cudaGetSymbolAddress((void**)&rc, g_rc);
    cudaGetSymbolAddress((void**)&rs, g_rs);

    cudaFuncSetAttribute(attention_kernel, cudaFuncAttributeMaxDynamicSharedMemorySize, ATT_SMEM);

    // weight transpose + split (runs inside graph each replay; ~6M elems)
    for (int l = 0; l < NLAYER; l++) {
        __nv_bfloat16* th = WThi + (size_t)l * WT_LAYER;
        __nv_bfloat16* tl = WTlo + (size_t)l * WT_LAYER;
        wsplit_kernel<<<dim3(16, 16), 256>>>(Wq + (size_t)l * DIM * DIM, th + WT_Q,  tl + WT_Q,  512, 512);
        wsplit_kernel<<<dim3(16, 16), 256>>>(Wk + (size_t)l * DIM * DIM, th + WT_K,  tl + WT_K,  512, 512);
        wsplit_kernel<<<dim3(16, 16), 256>>>(Wv + (size_t)l * DIM * DIM, th + WT_V,  tl + WT_V,  512, 512);
        wsplit_kernel<<<dim3(16, 16), 256>>>(Wo + (size_t)l * DIM * DIM, th + WT_O,  tl + WT_O,  512, 512);
        wsplit_kernel<<<dim3(64, 16), 256>>>(W1 + (size_t)l * DIM * FF,  th + WT_W1, tl + WT_W1, 512, 2048);
        wsplit_kernel<<<dim3(16, 64), 256>>>(W2 + (size_t)l * FF * DIM,  th + WT_W2, tl + WT_W2, 2048, 512);
    }
    rope_table_kernel<<<SEQ, 32>>>(rc, rs);
    cudaMemcpyAsync(X, x, sizeof(float) * (size_t)ROWS * DIM, cudaMemcpyDeviceToDevice, 0);

    dim3 g512(DIM / 128, ROWS / 128);   // (4, 64)
    dim3 gff (FF  / 128, ROWS / 128);   // (16, 64)

    for (int l = 0; l < NLAYER; l++) {
        const __nv_bfloat16* th = WThi + (size_t)l * WT_LAYER;
        const __nv_bfloat16* tl = WTlo + (size_t)l * WT_LAYER;

        rmsnorm_split_kernel<<<ROWS, 256>>>(X, ln1 + l * DIM, Ahi, Alo);
        hmma_gemm_kernel<0><<<g512, 256>>>(Ahi, Alo, th + WT_Q, tl + WT_Q,
                                           nullptr, Ql, nullptr, nullptr, ROWS, DIM, DIM);
        hmma_gemm_kernel<0><<<g512, 256>>>(Ahi, Alo, th + WT_K, tl + WT_K,
                                           nullptr, Kl, nullptr, nullptr, ROWS, DIM, DIM);
        hmma_gemm_kernel<0><<<g512, 256>>>(Ahi, Alo, th + WT_V, tl + WT_V,
                                           nullptr, Vl, nullptr, nullptr, ROWS, DIM, DIM);
        rope_kernel  <<<ROWS, 256>>>(Ql, Qr, rc, rs);
        rope_kernel  <<<ROWS, 256>>>(Kl, Kr, rc, rs);
        vtrans_kernel<<<ROWS, 256>>>(Vl, Vr);
        attention_kernel<<<dim3(SEQ / 64, NUM_B * NH), 256, ATT_SMEM>>>(Qr, Kr, Vr, Ahi, Alo);
        hmma_gemm_kernel<1><<<g512, 256>>>(Ahi, Alo, th + WT_O, tl + WT_O,
                                           X, X, nullptr, nullptr, ROWS, DIM, DIM);
        rmsnorm_split_kernel<<<ROWS, 256>>>(X, ln2 + l * DIM, Ahi, Alo);
        hmma_gemm_kernel<3><<<gff, 256>>>(Ahi, Alo, th + WT_W1, tl + WT_W1,
                                          nullptr, nullptr, Ghi, Glo, ROWS, FF, DIM);
        hmma_gemm_kernel<1><<<g512, 256>>>(Ghi, Glo, th + WT_W2, tl + WT_W2,
                                           X, X, nullptr, nullptr, ROWS, DIM, FF);
    }

    head_kernel <<<ROWS / 8, 256>>>(X, hw, hb, probs);
    chunk_kernel<<<NUM_B, 256>>>(probs, ids, nch, psum);
    mask_kernel <<<(N_MASK / 4) / 256, 256>>>(ids, out + OFF_MASK);
    scalars_kernel<<<1, 1>>>(nch, psum, out + OFF_ACL, out + OFF_CLL);
    xids_kernel <<<ROWS / 256, 256>>>(xids, out + OFF_IDS);
    cudaMemcpyAsync(out + OFF_XT, X, sizeof(float) * (size_t)ROWS * DIM, cudaMemcpyDeviceToDevice, 0);
}

// round 5
// speedup vs baseline: 3.6278x; 1.4612x over previous
#include <cuda_runtime.h>
#include <cuda_bf16.h>
#include <math.h>
#include <stdint.h>
#include <stddef.h>

// ---------------- problem constants ----------------
#define NUM_B 4
#define SEQ   2048
#define DIM   512
#define NH    8
#define DHD   64
#define FF    2048
#define ROWS  (NUM_B*SEQ)          // 8192
#define NLAYER 2

// output layout (float32, concatenated in reference return order)
#define OFF_XT   0
#define N_XT     (ROWS*DIM)                 // 4194304
#define OFF_IDS  (OFF_XT + N_XT)            // 4194304
#define N_IDS    (ROWS)                     // 8192
#define OFF_ACL  (OFF_IDS + N_IDS)          // 4202496
#define OFF_MASK (OFF_ACL + 1)              // 4202497 (odd -> scalar stores only)
#define N_MASK   (NUM_B*SEQ*SEQ)            // 16777216
#define OFF_CLL  (OFF_MASK + N_MASK)        // 20979713

// per-layer transposed-weight bf16 buffer layout (elements)
#define WT_Q   0
#define WT_K   (512*512)
#define WT_V   (2*512*512)
#define WT_O   (3*512*512)
#define WT_W1  (4*512*512)                  // [2048][512]
#define WT_W2  (4*512*512 + 2048*512)       // [512][2048]
#define WT_LAYER (4*512*512 + 2*2048*512)   // 3145728

// ---------------- scratch (device globals; no allocation allowed) ----------------
__device__ float g_X [ROWS*DIM];
__device__ float g_Ql[ROWS*DIM];
__device__ float g_Kl[ROWS*DIM];
__device__ float g_Vl[ROWS*DIM];
__device__ __nv_bfloat16 g_Qbh[ROWS*DIM];   // (B,H,S,Dh) hi, pre-scaled 1/8
__device__ __nv_bfloat16 g_Qbl[ROWS*DIM];
__device__ __nv_bfloat16 g_Kbh[ROWS*DIM];   // (B,H,S,Dh)
__device__ __nv_bfloat16 g_Kbl[ROWS*DIM];
__device__ __nv_bfloat16 g_Vbh[ROWS*DIM];   // (B,H,Dh,S)
__device__ __nv_bfloat16 g_Vbl[ROWS*DIM];
__device__ __nv_bfloat16 g_Ahi[ROWS*DIM];
__device__ __nv_bfloat16 g_Alo[ROWS*DIM];
__device__ __nv_bfloat16 g_Ghi[ROWS*FF];
__device__ __nv_bfloat16 g_Glo[ROWS*FF];
__device__ __nv_bfloat16 g_WThi[NLAYER*WT_LAYER];
__device__ __nv_bfloat16 g_WTlo[NLAYER*WT_LAYER];
__device__ float g_probs[ROWS];
__device__ int   g_ids[ROWS];
__device__ int   g_nch[NUM_B];
__device__ float g_psum[NUM_B];
__device__ float g_rc[SEQ*32];
__device__ float g_rs[SEQ*32];

// ---------------- mma.sync helper (bf16 x bf16 -> fp32, m16n8k16) ----------------
__device__ __forceinline__ void mma16816(float* c, const uint32_t* a, const uint32_t* b) {
    asm volatile(
        "mma.sync.aligned.m16n8k16.row.col.f32.bf16.bf16.f32 "
        "{%0,%1,%2,%3}, {%4,%5,%6,%7}, {%8,%9}, {%0,%1,%2,%3};"
        : "+f"(c[0]), "+f"(c[1]), "+f"(c[2]), "+f"(c[3])
        : "r"(a[0]), "r"(a[1]), "r"(a[2]), "r"(a[3]), "r"(b[0]), "r"(b[1]));
}

__device__ __forceinline__ uint32_t pack_bf16x2(float x, float y) {
    __nv_bfloat162 t;
    t.x = __float2bfloat16(x);
    t.y = __float2bfloat16(y);
    return *(uint32_t*)&t;
}

// ---------------- HMMA GEMM: C[M,N] = (Ahi+Alo) @ (Bhi+Blo)^T ----------------
// EPI: 0 = store fp32, 1 = residual add (Cin may alias C), 3 = gelu -> bf16 hi/lo split
#define SKP 40   // padded smem row stride (elements)

template<int EPI>
__global__ __launch_bounds__(256)
void hmma_gemm_kernel(const __nv_bfloat16* __restrict__ Ahi, const __nv_bfloat16* __restrict__ Alo,
                      const __nv_bfloat16* __restrict__ Bhi, const __nv_bfloat16* __restrict__ Blo,
                      const float* __restrict__ Cin, float* __restrict__ C,
                      __nv_bfloat16* __restrict__ Ghi, __nv_bfloat16* __restrict__ Glo,
                      int M, int N, int K) {
    __shared__ __align__(16) __nv_bfloat16 sAh[128 * SKP];
    __shared__ __align__(16) __nv_bfloat16 sAl[128 * SKP];
    __shared__ __align__(16) __nv_bfloat16 sBh[128 * SKP];
    __shared__ __align__(16) __nv_bfloat16 sBl[128 * SKP];

    const int tid = threadIdx.x;
    const int bm = blockIdx.y * 128, bn = blockIdx.x * 128;
    const int w = tid >> 5, lane = tid & 31;
    const int wm = (w & 1) * 64;
    const int wn = (w >> 1) * 32;
    const int g = lane >> 2;
    const int tg = lane & 3;

    float acc[4][4][4] = {};

    const int nchunk = K >> 5;
    for (int kc = 0; kc < nchunk; kc++) {
        for (int idx = tid; idx < 512; idx += 256) {
            int r = idx >> 2;
            int ko = (idx & 3) << 3;
            size_t ga = (size_t)(bm + r) * K + (size_t)kc * 32 + ko;
            size_t gb = (size_t)(bn + r) * K + (size_t)kc * 32 + ko;
            *(uint4*)&sAh[r * SKP + ko] = *(const uint4*)(Ahi + ga);
            *(uint4*)&sAl[r * SKP + ko] = *(const uint4*)(Alo + ga);
            *(uint4*)&sBh[r * SKP + ko] = *(const uint4*)(Bhi + gb);
            *(uint4*)&sBl[r * SKP + ko] = *(const uint4*)(Blo + gb);
        }
        __syncthreads();
#pragma unroll
        for (int ks = 0; ks < 2; ks++) {
            const int kk = ks * 16 + tg * 2;
            uint32_t bh[4][2], bl[4][2];
#pragma unroll
            for (int nt = 0; nt < 4; nt++) {
                int nr = wn + nt * 8 + g;
                bh[nt][0] = *(const uint32_t*)&sBh[nr * SKP + kk];
                bh[nt][1] = *(const uint32_t*)&sBh[nr * SKP + kk + 8];
                bl[nt][0] = *(const uint32_t*)&sBl[nr * SKP + kk];
                bl[nt][1] = *(const uint32_t*)&sBl[nr * SKP + kk + 8];
            }
#pragma unroll
            for (int mt = 0; mt < 4; mt++) {
                int r0 = wm + mt * 16 + g;
                int r1 = r0 + 8;
                uint32_t ah[4], al[4];
                ah[0] = *(const uint32_t*)&sAh[r0 * SKP + kk];
                ah[1] = *(const uint32_t*)&sAh[r1 * SKP + kk];
                ah[2] = *(const uint32_t*)&sAh[r0 * SKP + kk + 8];
                ah[3] = *(const uint32_t*)&sAh[r1 * SKP + kk + 8];
                al[0] = *(const uint32_t*)&sAl[r0 * SKP + kk];
                al[1] = *(const uint32_t*)&sAl[r1 * SKP + kk];
                al[2] = *(const uint32_t*)&sAl[r0 * SKP + kk + 8];
                al[3] = *(const uint32_t*)&sAl[r1 * SKP + kk + 8];
#pragma unroll
                for (int nt = 0; nt < 4; nt++) {
                    mma16816(acc[mt][nt], ah, bh[nt]);
                    mma16816(acc[mt][nt], ah, bl[nt]);
                    mma16816(acc[mt][nt], al, bh[nt]);
                }
            }
        }
        __syncthreads();
    }

#pragma unroll
    for (int mt = 0; mt < 4; mt++) {
        int row0 = bm + wm + mt * 16 + g;
        int row1 = row0 + 8;
#pragma unroll
        for (int nt = 0; nt < 4; nt++) {
            int col = bn + wn + nt * 8 + tg * 2;
            float c0 = acc[mt][nt][0], c1 = acc[mt][nt][1];
            float c2 = acc[mt][nt][2], c3 = acc[mt][nt][3];
            if (EPI == 0 || EPI == 1) {
                if (EPI == 1) {
                    float2 r0 = *(const float2*)(Cin + (size_t)row0 * N + col);
                    float2 r1 = *(const float2*)(Cin + (size_t)row1 * N + col);
                    c0 += r0.x; c1 += r0.y; c2 += r1.x; c3 += r1.y;
                }
                float2 v0 = {c0, c1}, v1 = {c2, c3};
                *(float2*)(C + (size_t)row0 * N + col) = v0;
                *(float2*)(C + (size_t)row1 * N + col) = v1;
            } else {
                float vv[4] = {c0, c1, c2, c3};
                __nv_bfloat16 h[4], l[4];
#pragma unroll
                for (int e = 0; e < 4; e++) {
                    float v = vv[e];
                    v = 0.5f * v * (1.0f + erff(v * 0.70710678118654752f));
                    h[e] = __float2bfloat16(v);
                    l[e] = __float2bfloat16(v - __bfloat162float(h[e]));
                }
                *(__nv_bfloat162*)(Ghi + (size_t)row0 * N + col) = {h[0], h[1]};
                *(__nv_bfloat162*)(Ghi + (size_t)row1 * N + col) = {h[2], h[3]};
                *(__nv_bfloat162*)(Glo + (size_t)row0 * N + col) = {l[0], l[1]};
                *(__nv_bfloat162*)(Glo + (size_t)row1 * N + col) = {l[2], l[3]};
            }
        }
    }
}

// ---------------- weight transpose + bf16 hi/lo split: W[K][N] -> T[N][K] ----------------
__global__ void wsplit_kernel(const float* __restrict__ W, __nv_bfloat16* __restrict__ Th,
                              __nv_bfloat16* __restrict__ Tl, int K, int N) {
    __shared__ float tile[32][33];
    int n0 = blockIdx.x * 32, k0 = blockIdx.y * 32;
    int tx = threadIdx.x & 31, ty = threadIdx.x >> 5;
#pragma unroll
    for (int i = 0; i < 32; i += 8)
        tile[ty + i][tx] = W[(size_t)(k0 + ty + i) * N + n0 + tx];
    __syncthreads();
#pragma unroll
    for (int i = 0; i < 32; i += 8) {
        float v = tile[tx][ty + i];
        __nv_bfloat16 h = __float2bfloat16(v);
        __nv_bfloat16 l = __float2bfloat16(v - __bfloat162float(h));
        size_t o = (size_t)(n0 + ty + i) * K + k0 + tx;
        Th[o] = h; Tl[o] = l;
    }
}

// ---------------- rope table ----------------
__global__ void rope_table_kernel(float* __restrict__ ct, float* __restrict__ st) {
    int i = threadIdx.x;
    int s = blockIdx.x;
    double inv = pow(10000.0, -(double)i / 32.0);
    double ang = (double)s * inv;
    double sn, cs;
    sincos(ang, &sn, &cs);
    ct[s * 32 + i] = (float)cs;
    st[s * 32 + i] = (float)sn;
}

// ---------------- rmsnorm + bf16 hi/lo split ----------------
__global__ void rmsnorm_split_kernel(const float* __restrict__ x, const float* __restrict__ w,
                                     __nv_bfloat16* __restrict__ hi, __nv_bfloat16* __restrict__ lo) {
    int row = blockIdx.x;
    int t = threadIdx.x;
    const float* xr = x + (size_t)row * DIM;
    float v0 = xr[t], v1 = xr[t + 256];
    __shared__ float red[256];
    red[t] = v0 * v0 + v1 * v1;
    __syncthreads();
#pragma unroll
    for (int o = 128; o > 0; o >>= 1) {
        if (t < o) red[t] += red[t + o];
        __syncthreads();
    }
    float inv = rsqrtf(red[0] * (1.0f / (float)DIM) + 1e-6f);
    float y0 = v0 * inv * w[t];
    float y1 = v1 * inv * w[t + 256];
    __nv_bfloat16 h0 = __float2bfloat16(y0);
    __nv_bfloat16 h1 = __float2bfloat16(y1);
    size_t o0 = (size_t)row * DIM + t;
    hi[o0]       = h0;  lo[o0]       = __float2bfloat16(y0 - __bfloat162float(h0));
    hi[o0 + 256] = h1;  lo[o0 + 256] = __float2bfloat16(y1 - __bfloat162float(h1));
}

// ---------------- rope -> bf16 hi/lo, (B,S,H*Dh) -> (B,H,S,Dh), optional scale ----------
__global__ void rope_split_kernel(const float* __restrict__ lin,
                                  __nv_bfloat16* __restrict__ oh, __nv_bfloat16* __restrict__ ol,
                                  const float* __restrict__ ct, const float* __restrict__ st,
                                  float scale) {
    int bs = blockIdx.x;
    int s = bs & (SEQ - 1);
    int b = bs >> 11;
    int h = threadIdx.x >> 5;
    int i = threadIdx.x & 31;
    const float* src = lin + (size_t)bs * DIM + h * DHD;
    float t1 = src[i], t2 = src[i + 32];
    float c  = ct[s * 32 + i];
    float si = st[s * 32 + i];
    float y0 = (t1 * c - t2 * si) * scale;
    float y1 = (t1 * si + t2 * c) * scale;
    size_t base = (((size_t)(b * NH + h)) * SEQ + s) * DHD;
    __nv_bfloat16 h0 = __float2bfloat16(y0);
    __nv_bfloat16 h1 = __float2bfloat16(y1);
    oh[base + i]      = h0;  ol[base + i]      = __float2bfloat16(y0 - __bfloat162float(h0));
    oh[base + i + 32] = h1;  ol[base + i + 32] = __float2bfloat16(y1 - __bfloat162float(h1));
}

// ---------------- V transpose: (B,S,H*Dh) fp32 -> (B,H,Dh,S) bf16 hi/lo ----------------
__global__ void vtrans_split_kernel(const float* __restrict__ lin,
                                    __nv_bfloat16* __restrict__ oh, __nv_bfloat16* __restrict__ ol) {
    __shared__ float tile[64][65];
    int s0 = blockIdx.x * 64;
    int bh = blockIdx.y;
    int b = bh >> 3, h = bh & 7;
    int tid = threadIdx.x;
    for (int idx = tid; idx < 1024; idx += 256) {
        int r = idx >> 4, c4 = (idx & 15) << 2;
        float4 v = *(const float4*)(lin + ((size_t)(b * SEQ + s0 + r)) * DIM + h * DHD + c4);
        tile[r][c4 + 0] = v.x; tile[r][c4 + 1] = v.y;
        tile[r][c4 + 2] = v.z; tile[r][c4 + 3] = v.w;
    }
    __syncthreads();
    for (int idx = tid; idx < 2048; idx += 256) {
        int d = idx >> 5, sp = (idx & 31) << 1;
        float v0 = tile[sp][d], v1 = tile[sp + 1][d];
        __nv_bfloat16 h0 = __float2bfloat16(v0), h1 = __float2bfloat16(v1);
        float l0 = v0 - __bfloat162float(h0), l1 = v1 - __bfloat162float(h1);
        size_t o = ((size_t)bh * DHD + d) * SEQ + s0 + sp;
        *(__nv_bfloat162*)(oh + o) = {h0, h1};
        *(__nv_bfloat162*)(ol + o) = {__float2bfloat16(l0), __float2bfloat16(l1)};
    }
}

// ---------------- HMMA flash attention ----------------
// 64 q-rows/CTA, 4 warps (16 rows each), causal, online softmax in registers.
// Q pre-scaled by 1/8. Outputs bf16 hi/lo in (B,S,D) for the Wo GEMM.
#define AT_STR 72
#define FA_SMEM (4 * 64 * AT_STR * 2)   // 36864 bytes (sKh, sKl, sVh, sVl)

__global__ __launch_bounds__(128)
void fa_kernel(const __nv_bfloat16* __restrict__ Qh, const __nv_bfloat16* __restrict__ Ql,
               const __nv_bfloat16* __restrict__ Kh, const __nv_bfloat16* __restrict__ Kl,
               const __nv_bfloat16* __restrict__ Vh, const __nv_bfloat16* __restrict__ Vl,
               __nv_bfloat16* __restrict__ Ohi, __nv_bfloat16* __restrict__ Olo) {
    extern __shared__ __nv_bfloat16 smb[];
    __nv_bfloat16* sKh = smb;
    __nv_bfloat16* sKl = smb + 64 * AT_STR;
    __nv_bfloat16* sVh = smb + 2 * 64 * AT_STR;
    __nv_bfloat16* sVl = smb + 3 * 64 * AT_STR;

    const int qt = blockIdx.x, bh = blockIdx.y;
    const int tid = threadIdx.x, w = tid >> 5, lane = tid & 31;
    const int g = lane >> 2, tg = lane & 3;

    // ---- stage Q (into K buffers), extract fragments ----
    {
        const __nv_bfloat16* qbh = Qh + ((size_t)bh * SEQ + qt * 64) * DHD;
        const __nv_bfloat16* qbl = Ql + ((size_t)bh * SEQ + qt * 64) * DHD;
        for (int idx = tid; idx < 512; idx += 128) {
            int r = idx >> 3, c = (idx & 7) << 3;
            *(uint4*)&sKh[r * AT_STR + c] = *(const uint4*)(qbh + r * DHD + c);
            *(uint4*)&sKl[r * AT_STR + c] = *(const uint4*)(qbl + r * DHD + c);
        }
    }
    __syncthreads();
    uint32_t aQh[4][4], aQl[4][4];
    {
        int r0 = w * 16 + g, r1 = r0 + 8;
#pragma unroll
        for (int kc = 0; kc < 4; kc++) {
            int kk = kc * 16 + tg * 2;
            aQh[kc][0] = *(const uint32_t*)&sKh[r0 * AT_STR + kk];
            aQh[kc][1] = *(const uint32_t*)&sKh[r1 * AT_STR + kk];
            aQh[kc][2] = *(const uint32_t*)&sKh[r0 * AT_STR + kk + 8];
            aQh[kc][3] = *(const uint32_t*)&sKh[r1 * AT_STR + kk + 8];
            aQl[kc][0] = *(const uint32_t*)&sKl[r0 * AT_STR + kk];
            aQl[kc][1] = *(const uint32_t*)&sKl[r1 * AT_STR + kk];
            aQl[kc][2] = *(const uint32_t*)&sKl[r0 * AT_STR + kk + 8];
            aQl[kc][3] = *(const uint32_t*)&sKl[r1 * AT_STR + kk + 8];
        }
    }
    __syncthreads();

    float accO[8][4] = {};
    float m0 = -1e30f, m1 = -1e30f, l0 = 0.f, l1 = 0.f;
    const int lrow0 = w * 16 + g;        // local q row (within 64-tile)
    const int lrow1 = lrow0 + 8;

    const __nv_bfloat16* kbh = Kh + (size_t)bh * SEQ * DHD;
    const __nv_bfloat16* kbl = Kl + (size_t)bh * SEQ * DHD;
    const __nv_bfloat16* vbh = Vh + (size_t)bh * DHD * SEQ;
    const __nv_bfloat16* vbl = Vl + (size_t)bh * DHD * SEQ;

    for (int kt = 0; kt <= qt; kt++) {
        // stage K [key][d], V [d][key]
        for (int idx = tid; idx < 512; idx += 128) {
            int r = idx >> 3, c = (idx & 7) << 3;
            *(uint4*)&sKh[r * AT_STR + c] = *(const uint4*)(kbh + (size_t)(kt * 64 + r) * DHD + c);
            *(uint4*)&sKl[r * AT_STR + c] = *(const uint4*)(kbl + (size_t)(kt * 64 + r) * DHD + c);
            *(uint4*)&sVh[r * AT_STR + c] = *(const uint4*)(vbh + (size_t)r * SEQ + kt * 64 + c);
            *(uint4*)&sVl[r * AT_STR + c] = *(const uint4*)(vbl + (size_t)r * SEQ + kt * 64 + c);
        }
        __syncthreads();

        // S = Q @ K^T
        float sc[8][4] = {};
#pragma unroll
        for (int nt = 0; nt < 8; nt++) {
            int nr = nt * 8 + g;
#pragma unroll
            for (int kc = 0; kc < 4; kc++) {
                int kk = kc * 16 + tg * 2;
                uint32_t bkh[2], bkl[2];
                bkh[0] = *(const uint32_t*)&sKh[nr * AT_STR + kk];
                bkh[1] = *(const uint32_t*)&sKh[nr * AT_STR + kk + 8];
                bkl[0] = *(const uint32_t*)&sKl[nr * AT_STR + kk];
                bkl[1] = *(const uint32_t*)&sKl[nr * AT_STR + kk + 8];
                mma16816(sc[nt], aQh[kc], bkh);
                mma16816(sc[nt], aQh[kc], bkl);
                mma16816(sc[nt], aQl[kc], bkh);
            }
        }

        // causal mask on diagonal tile
        if (kt == qt) {
#pragma unroll
            for (int nt = 0; nt < 8; nt++) {
                int key = nt * 8 + tg * 2;
                if (key     > lrow0) sc[nt][0] = -1e30f;
                if (key + 1 > lrow0) sc[nt][1] = -1e30f;
                if (key     > lrow1) sc[nt][2] = -1e30f;
                if (key + 1 > lrow1) sc[nt][3] = -1e30f;
            }
        }

        // online softmax (row stats across quad lanes)
        float mt0 = -1e30f, mt1 = -1e30f;
#pragma unroll
        for (int nt = 0; nt < 8; nt++) {
            mt0 = fmaxf(mt0, fmaxf(sc[nt][0], sc[nt][1]));
            mt1 = fmaxf(mt1, fmaxf(sc[nt][2], sc[nt][3]));
        }
        mt0 = fmaxf(mt0, __shfl_xor_sync(0xffffffffu, mt0, 1));
        mt0 = fmaxf(mt0, __shfl_xor_sync(0xffffffffu, mt0, 2));
        mt1 = fmaxf(mt1, __shfl_xor_sync(0xffffffffu, mt1, 1));
        mt1 = fmaxf(mt1, __shfl_xor_sync(0xffffffffu, mt1, 2));
        float mn0 = fmaxf(m0, mt0), mn1 = fmaxf(m1, mt1);
        float f0 = __expf(m0 - mn0), f1 = __expf(m1 - mn1);
        float s0 = 0.f, s1 = 0.f;
#pragma unroll
        for (int nt = 0; nt < 8; nt++) {
            float p0 = __expf(sc[nt][0] - mn0);
            float p1 = __expf(sc[nt][1] - mn0);
            float p2 = __expf(sc[nt][2] - mn1);
            float p3 = __expf(sc[nt][3] - mn1);
            sc[nt][0] = p0; sc[nt][1] = p1; sc[nt][2] = p2; sc[nt][3] = p3;
            s0 += p0 + p1; s1 += p2 + p3;
        }
        s0 += __shfl_xor_sync(0xffffffffu, s0, 1);
        s0 += __shfl_xor_sync(0xffffffffu, s0, 2);
        s1 += __shfl_xor_sync(0xffffffffu, s1, 1);
        s1 += __shfl_xor_sync(0xffffffffu, s1, 2);
        l0 = l0 * f0 + s0;
        l1 = l1 * f1 + s1;
        m0 = mn0; m1 = mn1;
#pragma unroll
        for (int dt = 0; dt < 8; dt++) {
            accO[dt][0] *= f0; accO[dt][1] *= f0;
            accO[dt][2] *= f1; accO[dt][3] *= f1;
        }

        // O += P @ V  (P split hi/lo in registers)
#pragma unroll
        for (int j = 0; j < 4; j++) {
            float x00 = sc[2*j][0],   x01 = sc[2*j][1],   x02 = sc[2*j][2],   x03 = sc[2*j][3];
            float x10 = sc[2*j+1][0], x11 = sc[2*j+1][1], x12 = sc[2*j+1][2], x13 = sc[2*j+1][3];
            uint32_t aPh[4], aPl[4];
            aPh[0] = pack_bf16x2(x00, x01);
            aPh[1] = pack_bf16x2(x02, x03);
            aPh[2] = pack_bf16x2(x10, x11);
            aPh[3] = pack_bf16x2(x12, x13);
            __nv_bfloat162* t;
            t = (__nv_bfloat162*)&aPh[0];
            aPl[0] = pack_bf16x2(x00 - __bfloat162float(t->x), x01 - __bfloat162float(t->y));
            t = (__nv_bfloat162*)&aPh[1];
            aPl[1] = pack_bf16x2(x02 - __bfloat162float(t->x), x03 - __bfloat162float(t->y));
            t = (__nv_bfloat162*)&aPh[2];
            aPl[2] = pack_bf16x2(x10 - __bfloat162float(t->x), x11 - __bfloat162float(t->y));
            t = (__nv_bfloat162*)&aPh[3];
            aPl[3] = pack_bf16x2(x12 - __bfloat162float(t->x), x13 - __bfloat162float(t->y));
            int kk = j * 16 + tg * 2;
#pragma unroll
            for (int dt = 0; dt < 8; dt++) {
                int nr = dt * 8 + g;
                uint32_t bvh[2], bvl[2];
                bvh[0] = *(const uint32_t*)&sVh[nr * AT_STR + kk];
                bvh[1] = *(const uint32_t*)&sVh[nr * AT_STR + kk + 8];
                bvl[0] = *(const uint32_t*)&sVl[nr * AT_STR + kk];
                bvl[1] = *(const uint32_t*)&sVl[nr * AT_STR + kk + 8];
                mma16816(accO[dt], aPh, bvh);
                mma16816(accO[dt], aPh, bvl);
                mma16816(accO[dt], aPl, bvh);
            }
        }
        __syncthreads();
    }

    // epilogue -> (B,S,D) bf16 hi/lo
    float il0 = 1.0f / l0, il1 = 1.0f / l1;
    int b = bh >> 3, h = bh & 7;
    size_t row0 = (size_t)b * SEQ + qt * 64 + w * 16 + g;
    size_t row1 = row0 + 8;
#pragma unroll
    for (int dt = 0; dt < 8; dt++) {
        int col = h * DHD + dt * 8 + tg * 2;
        float o0 = accO[dt][0] * il0, o1 = accO[dt][1] * il0;
        float o2 = accO[dt][2] * il1, o3 = accO[dt][3] * il1;
        __nv_bfloat16 h0 = __float2bfloat16(o0), h1 = __float2bfloat16(o1);
        __nv_bfloat16 h2 = __float2bfloat16(o2), h3 = __float2bfloat16(o3);
        *(__nv_bfloat162*)(Ohi + row0 * DIM + col) = {h0, h1};
        *(__nv_bfloat162*)(Ohi + row1 * DIM + col) = {h2, h3};
        *(__nv_bfloat162*)(Olo + row0 * DIM + col) =
            {__float2bfloat16(o0 - __bfloat162float(h0)), __float2bfloat16(o1 - __bfloat162float(h1))};
        *(__nv_bfloat162*)(Olo + row1 * DIM + col) =
            {__float2bfloat16(o2 - __bfloat162float(h2)), __float2bfloat16(o3 - __bfloat162float(h3))};
    }
}

// ---------------- head: logits -> sigmoid probs ----------------
__global__ void head_kernel(const float* __restrict__ X, const float* __restrict__ hw,
                            const float* __restrict__ hb, float* __restrict__ probs) {
    int row = blockIdx.x * 8 + (threadIdx.x >> 5);
    int lane = threadIdx.x & 31;
    const float* xr = X + (size_t)row * DIM;
    float s = 0.f;
    for (int i = lane; i < DIM; i += 32) s = fmaf(xr[i], hw[i], s);
#pragma unroll
    for (int o = 16; o; o >>= 1) s += __shfl_xor_sync(0xffffffffu, s, o);
    if (lane == 0) {
        float logit = s + hb[0];
        probs[row] = 1.0f / (1.0f + expf(-logit));
    }
}

// ---------------- chunking ----------------
__global__ void chunk_kernel(const float* __restrict__ probs, int* __restrict__ ids,
                             int* __restrict__ nch, float* __restrict__ psum) {
    int b = blockIdx.x, t = threadIdx.x;
    __shared__ int flags[SEQ];
    __shared__ float red[256];
    const float* pr = probs + (size_t)b * SEQ;
    float s = 0.f; int any = 0;
    for (int i = t; i < SEQ; i += 256) {
        float p = pr[i];
        int f = (p > 0.5f) ? 1 : 0;
        flags[i] = f; s += p; any |= f;
    }
    red[t] = s;
    __syncthreads();
#pragma unroll
    for (int o = 128; o > 0; o >>= 1) {
        if (t < o) red[t] += red[t + o];
        __syncthreads();
    }
    int anyflag = __syncthreads_or(any);
    if (t == 0) {
        psum[b] = red[0];
        int cur_end = 0, cid = -1;
        for (int tt = 0; tt < SEQ; tt++) {
            if (tt == cur_end) {
                int cap = tt + 16; if (cap > SEQ) cap = SEQ;
                int e = cap;
                for (int ss = tt + 1; ss <= cap; ss++) {
                    int he = anyflag ? flags[ss - 1] : (ss == SEQ - 1);
                    if (he) { e = ss; break; }
                }
                if (e - tt < 3) { e = tt + 3; if (e > SEQ) e = SEQ; }
                cur_end = e; cid++;
            }
            ids[b * SEQ + tt] = cid;
        }
        nch[b] = cid + 1;
    }
}

// ---------------- mask ----------------
__global__ void mask_kernel(const int* __restrict__ ids, float* __restrict__ out) {
    int i4 = blockIdx.x * 256 + threadIdx.x;
    int j = (i4 & 511) << 2;
    int rowIdx = i4 >> 9;
    int b = rowIdx >> 11;
    int idi = ids[rowIdx];
    const int* idr = ids + b * SEQ;
    size_t base = ((size_t)rowIdx << 11) + j;
    out[base + 0] = (idi == idr[j + 0]) ? 1.f : 0.f;
    out[base + 1] = (idi == idr[j + 1]) ? 1.f : 0.f;
    out[base + 2] = (idi == idr[j + 2]) ? 1.f : 0.f;
    out[base + 3] = (idi == idr[j + 3]) ? 1.f : 0.f;
}

__global__ void scalars_kernel(const int* __restrict__ nch, const float* __restrict__ psum,
                               float* __restrict__ out_acl, float* __restrict__ out_cll) {
    float a = 0.f, c = 0.f;
    for (int b = 0; b < NUM_B; b++) {
        a += (float)SEQ / (float)nch[b];
        c += psum[b];
    }
    *out_acl = a * 0.25f;
    *out_cll = c * 0.25f;
}

__global__ void xids_kernel(const int* __restrict__ xids, float* __restrict__ out) {
    int i = blockIdx.x * 256 + threadIdx.x;
    out[i] = (float)xids[i];
}

// ---------------- launch ----------------
extern "C" void kernel_launch(void* const* d_in, const int* in_sizes, int n_in,
                              void* d_out, int out_size) {
    const float* x    = (const float*)d_in[0];
    const int*   xids = (const int*)  d_in[1];
    const float* ln1  = (const float*)d_in[2];
    const float* Wq   = (const float*)d_in[3];
    const float* Wk   = (const float*)d_in[4];
    const float* Wv   = (const float*)d_in[5];
    const float* Wo   = (const float*)d_in[6];
    const float* ln2  = (const float*)d_in[7];
    const float* W1   = (const float*)d_in[8];
    const float* W2   = (const float*)d_in[9];
    const float* hw   = (const float*)d_in[10];
    const float* hb   = (const float*)d_in[11];
    float* out = (float*)d_out;

    float *X, *Ql, *Kl, *Vl, *probs, *psum, *rc, *rs;
    __nv_bfloat16 *Ahi, *Alo, *Ghi, *Glo, *WThi, *WTlo;
    __nv_bfloat16 *Qbh, *Qbl, *Kbh, *Kbl, *Vbh, *Vbl;
    int *ids, *nch;
    cudaGetSymbolAddress((void**)&X,  g_X);
    cudaGetSymbolAddress((void**)&Ql, g_Ql);
    cudaGetSymbolAddress((void**)&Kl, g_Kl);
    cudaGetSymbolAddress((void**)&Vl, g_Vl);
    cudaGetSymbolAddress((void**)&Qbh, g_Qbh);
    cudaGetSymbolAddress((void**)&Qbl, g_Qbl);
    cudaGetSymbolAddress((void**)&Kbh, g_Kbh);
    cudaGetSymbolAddress((void**)&Kbl, g_Kbl);
    cudaGetSymbolAddress((void**)&Vbh, g_Vbh);
    cudaGetSymbolAddress((void**)&Vbl, g_Vbl);
    cudaGetSymbolAddress((void**)&Ahi, g_Ahi);
    cudaGetSymbolAddress((void**)&Alo, g_Alo);
    cudaGetSymbolAddress((void**)&Ghi, g_Ghi);
    cudaGetSymbolAddress((void**)&Glo, g_Glo);
    cudaGetSymbolAddress((void**)&WThi, g_WThi);
    cudaGetSymbolAddress((void**)&WTlo, g_WTlo);
    cudaGetSymbolAddress((void**)&probs, g_probs);
    cudaGetSymbolAddress((void**)&psum,  g_psum);
    cudaGetSymbolAddress((void**)&ids, g_ids);
    cudaGetSymbolAddress((void**)&nch, g_nch);
    cudaGetSymbolAddress((void**)&rc, g_rc);
    cudaGetSymbolAddress((void**)&rs, g_rs);

    // weight transpose + split
    for (int l = 0; l < NLAYER; l++) {
        __nv_bfloat16* th = WThi + (size_t)l * WT_LAYER;
        __nv_bfloat16* tl = WTlo + (size_t)l * WT_LAYER;
        wsplit_kernel<<<dim3(16, 16), 256>>>(Wq + (size_t)l * DIM * DIM, th + WT_Q,  tl + WT_Q,  512, 512);
        wsplit_kernel<<<dim3(16, 16), 256>>>(Wk + (size_t)l * DIM * DIM, th + WT_K,  tl + WT_K,  512, 512);
        wsplit_kernel<<<dim3(16, 16), 256>>>(Wv + (size_t)l * DIM * DIM, th + WT_V,  tl + WT_V,  512, 512);
        wsplit_kernel<<<dim3(16, 16), 256>>>(Wo + (size_t)l * DIM * DIM, th + WT_O,  tl + WT_O,  512, 512);
        wsplit_kernel<<<dim3(64, 16), 256>>>(W1 + (size_t)l * DIM * FF,  th + WT_W1, tl + WT_W1, 512, 2048);
        wsplit_kernel<<<dim3(16, 64), 256>>>(W2 + (size_t)l * FF * DIM,  th + WT_W2, tl + WT_W2, 2048, 512);
    }
    rope_table_kernel<<<SEQ, 32>>>(rc, rs);
    cudaMemcpyAsync(X, x, sizeof(float) * (size_t)ROWS * DIM, cudaMemcpyDeviceToDevice, 0);

    dim3 g512(DIM / 128, ROWS / 128);   // (4, 64)
    dim3 gff (FF  / 128, ROWS / 128);   // (16, 64)

    for (int l = 0; l < NLAYER; l++) {
        const __nv_bfloat16* th = WThi + (size_t)l * WT_LAYER;
        const __nv_bfloat16* tl = WTlo + (size_t)l * WT_LAYER;

        rmsnorm_split_kernel<<<ROWS, 256>>>(X, ln1 + l * DIM, Ahi, Alo);
        hmma_gemm_kernel<0><<<g512, 256>>>(Ahi, Alo, th + WT_Q, tl + WT_Q,
                                           nullptr, Ql, nullptr, nullptr, ROWS, DIM, DIM);
        hmma_gemm_kernel<0><<<g512, 256>>>(Ahi, Alo, th + WT_K, tl + WT_K,
                                           nullptr, Kl, nullptr, nullptr, ROWS, DIM, DIM);
        hmma_gemm_kernel<0><<<g512, 256>>>(Ahi, Alo, th + WT_V, tl + WT_V,
                                           nullptr, Vl, nullptr, nullptr, ROWS, DIM, DIM);
        rope_split_kernel<<<ROWS, 256>>>(Ql, Qbh, Qbl, rc, rs, 0.125f);
        rope_split_kernel<<<ROWS, 256>>>(Kl, Kbh, Kbl, rc, rs, 1.0f);
        vtrans_split_kernel<<<dim3(SEQ / 64, NUM_B * NH), 256>>>(Vl, Vbh, Vbl);
        fa_kernel<<<dim3(SEQ / 64, NUM_B * NH), 128, FA_SMEM>>>(Qbh, Qbl, Kbh, Kbl, Vbh, Vbl,
                                                                Ahi, Alo);
        hmma_gemm_kernel<1><<<g512, 256>>>(Ahi, Alo, th + WT_O, tl + WT_O,
                                           X, X, nullptr, nullptr, ROWS, DIM, DIM);
        rmsnorm_split_kernel<<<ROWS, 256>>>(X, ln2 + l * DIM, Ahi, Alo);
        hmma_gemm_kernel<3><<<gff, 256>>>(Ahi, Alo, th + WT_W1, tl + WT_W1,
                                          nullptr, nullptr, Ghi, Glo, ROWS, FF, DIM);
        hmma_gemm_kernel<1><<<g512, 256>>>(Ghi, Glo, th + WT_W2, tl + WT_W2,
                                           X, X, nullptr, nullptr, ROWS, DIM, FF);
    }

    head_kernel <<<ROWS / 8, 256>>>(X, hw, hb, probs);
    chunk_kernel<<<NUM_B, 256>>>(probs, ids, nch, psum);
    mask_kernel <<<(N_MASK / 4) / 256, 256>>>(ids, out + OFF_MASK);
    scalars_kernel<<<1, 1>>>(nch, psum, out + OFF_ACL, out + OFF_CLL);
    xids_kernel <<<ROWS / 256, 256>>>(xids, out + OFF_IDS);
    cudaMemcpyAsync(out + OFF_XT, X, sizeof(float) * (size_t)ROWS * DIM, cudaMemcpyDeviceToDevice, 0);
}

// round 6
// speedup vs baseline: 3.9930x; 1.1007x over previous
#include <cuda_runtime.h>
#include <cuda_bf16.h>
#include <math.h>
#include <stdint.h>
#include <stddef.h>

// ---------------- problem constants ----------------
#define NUM_B 4
#define SEQ   2048
#define DIM   512
#define NH    8
#define DHD   64
#define FF    2048
#define ROWS  (NUM_B*SEQ)          // 8192
#define NLAYER 2

// output layout (float32, concatenated in reference return order)
#define OFF_XT   0
#define N_XT     (ROWS*DIM)                 // 4194304
#define OFF_IDS  (OFF_XT + N_XT)            // 4194304
#define N_IDS    (ROWS)                     // 8192
#define OFF_ACL  (OFF_IDS + N_IDS)          // 4202496
#define OFF_MASK (OFF_ACL + 1)              // 4202497 (odd -> scalar stores only)
#define N_MASK   (NUM_B*SEQ*SEQ)            // 16777216
#define OFF_CLL  (OFF_MASK + N_MASK)        // 20979713

// per-layer transposed-weight bf16 buffer layout (elements)
#define WT_Q   0
#define WT_K   (512*512)
#define WT_V   (2*512*512)
#define WT_O   (3*512*512)
#define WT_W1  (4*512*512)                  // [2048][512]
#define WT_W2  (4*512*512 + 2048*512)       // [512][2048]
#define WT_LAYER (4*512*512 + 2*2048*512)   // 3145728

// ---------------- scratch (device globals; no allocation allowed) ----------------
__device__ float g_X [ROWS*DIM];
__device__ float g_Ql[ROWS*DIM];
__device__ float g_Kl[ROWS*DIM];
__device__ float g_Vl[ROWS*DIM];
__device__ __nv_bfloat16 g_Qbh[ROWS*DIM];   // (B,H,S,Dh) hi, pre-scaled 1/8
__device__ __nv_bfloat16 g_Qbl[ROWS*DIM];
__device__ __nv_bfloat16 g_Kbh[ROWS*DIM];   // (B,H,S,Dh)
__device__ __nv_bfloat16 g_Kbl[ROWS*DIM];
__device__ __nv_bfloat16 g_Vbh[ROWS*DIM];   // (B,H,Dh,S)
__device__ __nv_bfloat16 g_Vbl[ROWS*DIM];
__device__ __nv_bfloat16 g_Ahi[ROWS*DIM];
__device__ __nv_bfloat16 g_Alo[ROWS*DIM];
__device__ __nv_bfloat16 g_Ghi[ROWS*FF];
__device__ __nv_bfloat16 g_Glo[ROWS*FF];
__device__ __nv_bfloat16 g_WThi[NLAYER*WT_LAYER];
__device__ __nv_bfloat16 g_WTlo[NLAYER*WT_LAYER];
__device__ float g_probs[ROWS];
__device__ int   g_ids[ROWS];
__device__ int   g_nch[NUM_B];
__device__ float g_psum[NUM_B];
__device__ float g_rc[SEQ*32];
__device__ float g_rs[SEQ*32];

// ---------------- low-level helpers ----------------
__device__ __forceinline__ void mma16816(float* c, const uint32_t* a, const uint32_t* b) {
    asm volatile(
        "mma.sync.aligned.m16n8k16.row.col.f32.bf16.bf16.f32 "
        "{%0,%1,%2,%3}, {%4,%5,%6,%7}, {%8,%9}, {%0,%1,%2,%3};"
        : "+f"(c[0]), "+f"(c[1]), "+f"(c[2]), "+f"(c[3])
        : "r"(a[0]), "r"(a[1]), "r"(a[2]), "r"(a[3]), "r"(b[0]), "r"(b[1]));
}

__device__ __forceinline__ uint32_t pack_bf16x2(float x, float y) {
    __nv_bfloat162 t;
    t.x = __float2bfloat16(x);
    t.y = __float2bfloat16(y);
    return *(uint32_t*)&t;
}

__device__ __forceinline__ uint32_t smem_u32(const void* p) {
    uint32_t a;
    asm("{ .reg .u64 t; cvta.to.shared.u64 t, %1; cvt.u32.u64 %0, t; }" : "=r"(a) : "l"(p));
    return a;
}

__device__ __forceinline__ void cp_async16(uint32_t saddr, const void* gaddr) {
    asm volatile("cp.async.ca.shared.global [%0], [%1], 16;" :: "r"(saddr), "l"(gaddr));
}
#define CP_COMMIT() asm volatile("cp.async.commit_group;" ::: "memory")
#define CP_WAIT1()  asm volatile("cp.async.wait_group 1;" ::: "memory")
#define CP_WAIT0()  asm volatile("cp.async.wait_group 0;" ::: "memory")

__device__ __forceinline__ void ldsm_x4(uint32_t* r, uint32_t saddr) {
    asm volatile("ldmatrix.sync.aligned.m8n8.x4.shared.b16 {%0,%1,%2,%3}, [%4];"
        : "=r"(r[0]), "=r"(r[1]), "=r"(r[2]), "=r"(r[3]) : "r"(saddr));
}
__device__ __forceinline__ void ldsm_x2(uint32_t* r, uint32_t saddr) {
    asm volatile("ldmatrix.sync.aligned.m8n8.x2.shared.b16 {%0,%1}, [%2];"
        : "=r"(r[0]), "=r"(r[1]) : "r"(saddr));
}

// ---------------- HMMA GEMM: C[M,N] = (Ahi+Alo) @ (Bhi+Blo)^T ----------------
// 128x128 CTA tile, BK=32, 2-stage cp.async pipeline, ldmatrix fragment loads.
// EPI: 0 = store fp32, 1 = residual add (Cin may alias C), 3 = gelu -> bf16 hi/lo split
#define SKP 40                       // padded smem row stride (elements); 80B
#define GBUF (128*SKP)               // elements per operand buffer
#define GSTAGE (4*GBUF)              // elements per stage (Ah,Al,Bh,Bl)
#define GM_SMEM2 (2*GSTAGE*2)        // 81920 bytes

template<int EPI>
__global__ __launch_bounds__(256)
void hmma_gemm_kernel(const __nv_bfloat16* __restrict__ Ahi, const __nv_bfloat16* __restrict__ Alo,
                      const __nv_bfloat16* __restrict__ Bhi, const __nv_bfloat16* __restrict__ Blo,
                      const float* __restrict__ Cin, float* __restrict__ C,
                      __nv_bfloat16* __restrict__ Ghi, __nv_bfloat16* __restrict__ Glo,
                      int M, int N, int K) {
    extern __shared__ __nv_bfloat16 smg[];
    const uint32_t sb = smem_u32(smg);

    const int tid = threadIdx.x;
    const int bm = blockIdx.y * 128, bn = blockIdx.x * 128;
    const int w = tid >> 5, lane = tid & 31;
    const int wm = (w & 1) * 64;
    const int wn = (w >> 1) * 32;
    const int g = lane >> 2;
    const int tg = lane & 3;

    // cp.async source row/col for this thread (2 iterations x 4 buffers)
    const int cr0 = tid >> 2, cko0 = (tid & 3) << 3;
    const int cr1 = (tid + 256) >> 2, cko1 = ((tid + 256) & 3) << 3;

    // ldmatrix per-lane byte offsets within a stage
    uint32_t aoff[2], boff[2];
    {
        int arow = (lane & 15), acol8 = (lane >> 4) << 3;
        int lb = lane & 15;
        int brow = (lb & 7), bcol8 = (lb >> 3) << 3;
#pragma unroll
        for (int ks = 0; ks < 2; ks++) {
            aoff[ks] = ((wm + arow) * SKP + ks * 16 + acol8) * 2;
            boff[ks] = ((wn + brow) * SKP + ks * 16 + bcol8) * 2 + 2 * GBUF * 2;
        }
    }

    float acc[4][4][4] = {};
    const int nchunk = K >> 5;

    // ---- prologue: stage chunk 0 into stage 0 ----
    {
        const __nv_bfloat16* pAh = Ahi + (size_t)bm * K;
        const __nv_bfloat16* pAl = Alo + (size_t)bm * K;
        const __nv_bfloat16* pBh = Bhi + (size_t)bn * K;
        const __nv_bfloat16* pBl = Blo + (size_t)bn * K;
        uint32_t s0 = sb + (cr0 * SKP + cko0) * 2;
        uint32_t s1 = sb + (cr1 * SKP + cko1) * 2;
        size_t g0 = (size_t)cr0 * K + cko0;
        size_t g1 = (size_t)cr1 * K + cko1;
        cp_async16(s0,                pAh + g0);
        cp_async16(s0 + GBUF * 2,     pAl + g0);
        cp_async16(s0 + 2 * GBUF * 2, pBh + g0);
        cp_async16(s0 + 3 * GBUF * 2, pBl + g0);
        cp_async16(s1,                pAh + g1);
        cp_async16(s1 + GBUF * 2,     pAl + g1);
        cp_async16(s1 + 2 * GBUF * 2, pBh + g1);
        cp_async16(s1 + 3 * GBUF * 2, pBl + g1);
        CP_COMMIT();
    }

    for (int kc = 0; kc < nchunk; kc++) {
        const int cur = kc & 1;
        if (kc + 1 < nchunk) {
            const int nxt = cur ^ 1;
            const __nv_bfloat16* pAh = Ahi + (size_t)bm * K + (size_t)(kc + 1) * 32;
            const __nv_bfloat16* pAl = Alo + (size_t)bm * K + (size_t)(kc + 1) * 32;
            const __nv_bfloat16* pBh = Bhi + (size_t)bn * K + (size_t)(kc + 1) * 32;
            const __nv_bfloat16* pBl = Blo + (size_t)bn * K + (size_t)(kc + 1) * 32;
            uint32_t stb = sb + nxt * GSTAGE * 2;
            uint32_t s0 = stb + (cr0 * SKP + cko0) * 2;
            uint32_t s1 = stb + (cr1 * SKP + cko1) * 2;
            size_t g0 = (size_t)cr0 * K + cko0;
            size_t g1 = (size_t)cr1 * K + cko1;
            cp_async16(s0,                pAh + g0);
            cp_async16(s0 + GBUF * 2,     pAl + g0);
            cp_async16(s0 + 2 * GBUF * 2, pBh + g0);
            cp_async16(s0 + 3 * GBUF * 2, pBl + g0);
            cp_async16(s1,                pAh + g1);
            cp_async16(s1 + GBUF * 2,     pAl + g1);
            cp_async16(s1 + 2 * GBUF * 2, pBh + g1);
            cp_async16(s1 + 3 * GBUF * 2, pBl + g1);
            CP_COMMIT();
            CP_WAIT1();
        } else {
            CP_WAIT0();
        }
        __syncthreads();

        const uint32_t stg = sb + cur * GSTAGE * 2;
#pragma unroll
        for (int ks = 0; ks < 2; ks++) {
            uint32_t bh[4][2], bl[4][2];
#pragma unroll
            for (int nt = 0; nt < 4; nt++) {
                ldsm_x2(bh[nt], stg + boff[ks] + nt * 8 * SKP * 2);
                ldsm_x2(bl[nt], stg + boff[ks] + nt * 8 * SKP * 2 + GBUF * 2);
            }
#pragma unroll
            for (int mt = 0; mt < 4; mt++) {
                uint32_t ah[4], al[4];
                ldsm_x4(ah, stg + aoff[ks] + mt * 16 * SKP * 2);
                ldsm_x4(al, stg + aoff[ks] + mt * 16 * SKP * 2 + GBUF * 2);
#pragma unroll
                for (int nt = 0; nt < 4; nt++) {
                    mma16816(acc[mt][nt], ah, bh[nt]);
                    mma16816(acc[mt][nt], ah, bl[nt]);
                    mma16816(acc[mt][nt], al, bh[nt]);
                }
            }
        }
        __syncthreads();
    }

    // epilogue
#pragma unroll
    for (int mt = 0; mt < 4; mt++) {
        int row0 = bm + wm + mt * 16 + g;
        int row1 = row0 + 8;
#pragma unroll
        for (int nt = 0; nt < 4; nt++) {
            int col = bn + wn + nt * 8 + tg * 2;
            float c0 = acc[mt][nt][0], c1 = acc[mt][nt][1];
            float c2 = acc[mt][nt][2], c3 = acc[mt][nt][3];
            if (EPI == 0 || EPI == 1) {
                if (EPI == 1) {
                    float2 r0 = *(const float2*)(Cin + (size_t)row0 * N + col);
                    float2 r1 = *(const float2*)(Cin + (size_t)row1 * N + col);
                    c0 += r0.x; c1 += r0.y; c2 += r1.x; c3 += r1.y;
                }
                float2 v0 = {c0, c1}, v1 = {c2, c3};
                *(float2*)(C + (size_t)row0 * N + col) = v0;
                *(float2*)(C + (size_t)row1 * N + col) = v1;
            } else {
                float vv[4] = {c0, c1, c2, c3};
                __nv_bfloat16 h[4], l[4];
#pragma unroll
                for (int e = 0; e < 4; e++) {
                    float v = vv[e];
                    v = 0.5f * v * (1.0f + erff(v * 0.70710678118654752f));
                    h[e] = __float2bfloat16(v);
                    l[e] = __float2bfloat16(v - __bfloat162float(h[e]));
                }
                *(__nv_bfloat162*)(Ghi + (size_t)row0 * N + col) = {h[0], h[1]};
                *(__nv_bfloat162*)(Ghi + (size_t)row1 * N + col) = {h[2], h[3]};
                *(__nv_bfloat162*)(Glo + (size_t)row0 * N + col) = {l[0], l[1]};
                *(__nv_bfloat162*)(Glo + (size_t)row1 * N + col) = {l[2], l[3]};
            }
        }
    }
}

// ---------------- weight transpose + bf16 hi/lo split: W[K][N] -> T[N][K] ----------------
__global__ void wsplit_kernel(const float* __restrict__ W, __nv_bfloat16* __restrict__ Th,
                              __nv_bfloat16* __restrict__ Tl, int K, int N) {
    __shared__ float tile[32][33];
    int n0 = blockIdx.x * 32, k0 = blockIdx.y * 32;
    int tx = threadIdx.x & 31, ty = threadIdx.x >> 5;
#pragma unroll
    for (int i = 0; i < 32; i += 8)
        tile[ty + i][tx] = W[(size_t)(k0 + ty + i) * N + n0 + tx];
    __syncthreads();
#pragma unroll
    for (int i = 0; i < 32; i += 8) {
        float v = tile[tx][ty + i];
        __nv_bfloat16 h = __float2bfloat16(v);
        __nv_bfloat16 l = __float2bfloat16(v - __bfloat162float(h));
        size_t o = (size_t)(n0 + ty + i) * K + k0 + tx;
        Th[o] = h; Tl[o] = l;
    }
}

// ---------------- rope table ----------------
__global__ void rope_table_kernel(float* __restrict__ ct, float* __restrict__ st) {
    int i = threadIdx.x;
    int s = blockIdx.x;
    double inv = pow(10000.0, -(double)i / 32.0);
    double ang = (double)s * inv;
    double sn, cs;
    sincos(ang, &sn, &cs);
    ct[s * 32 + i] = (float)cs;
    st[s * 32 + i] = (float)sn;
}

// ---------------- rmsnorm + bf16 hi/lo split ----------------
__global__ void rmsnorm_split_kernel(const float* __restrict__ x, const float* __restrict__ w,
                                     __nv_bfloat16* __restrict__ hi, __nv_bfloat16* __restrict__ lo) {
    int row = blockIdx.x;
    int t = threadIdx.x;
    const float* xr = x + (size_t)row * DIM;
    float v0 = xr[t], v1 = xr[t + 256];
    __shared__ float red[256];
    red[t] = v0 * v0 + v1 * v1;
    __syncthreads();
#pragma unroll
    for (int o = 128; o > 0; o >>= 1) {
        if (t < o) red[t] += red[t + o];
        __syncthreads();
    }
    float inv = rsqrtf(red[0] * (1.0f / (float)DIM) + 1e-6f);
    float y0 = v0 * inv * w[t];
    float y1 = v1 * inv * w[t + 256];
    __nv_bfloat16 h0 = __float2bfloat16(y0);
    __nv_bfloat16 h1 = __float2bfloat16(y1);
    size_t o0 = (size_t)row * DIM + t;
    hi[o0]       = h0;  lo[o0]       = __float2bfloat16(y0 - __bfloat162float(h0));
    hi[o0 + 256] = h1;  lo[o0 + 256] = __float2bfloat16(y1 - __bfloat162float(h1));
}

// ---------------- rope -> bf16 hi/lo, (B,S,H*Dh) -> (B,H,S,Dh), optional scale ----------
__global__ void rope_split_kernel(const float* __restrict__ lin,
                                  __nv_bfloat16* __restrict__ oh, __nv_bfloat16* __restrict__ ol,
                                  const float* __restrict__ ct, const float* __restrict__ st,
                                  float scale) {
    int bs = blockIdx.x;
    int s = bs & (SEQ - 1);
    int b = bs >> 11;
    int h = threadIdx.x >> 5;
    int i = threadIdx.x & 31;
    const float* src = lin + (size_t)bs * DIM + h * DHD;
    float t1 = src[i], t2 = src[i + 32];
    float c  = ct[s * 32 + i];
    float si = st[s * 32 + i];
    float y0 = (t1 * c - t2 * si) * scale;
    float y1 = (t1 * si + t2 * c) * scale;
    size_t base = (((size_t)(b * NH + h)) * SEQ + s) * DHD;
    __nv_bfloat16 h0 = __float2bfloat16(y0);
    __nv_bfloat16 h1 = __float2bfloat16(y1);
    oh[base + i]      = h0;  ol[base + i]      = __float2bfloat16(y0 - __bfloat162float(h0));
    oh[base + i + 32] = h1;  ol[base + i + 32] = __float2bfloat16(y1 - __bfloat162float(h1));
}

// ---------------- V transpose: (B,S,H*Dh) fp32 -> (B,H,Dh,S) bf16 hi/lo ----------------
__global__ void vtrans_split_kernel(const float* __restrict__ lin,
                                    __nv_bfloat16* __restrict__ oh, __nv_bfloat16* __restrict__ ol) {
    __shared__ float tile[64][65];
    int s0 = blockIdx.x * 64;
    int bh = blockIdx.y;
    int b = bh >> 3, h = bh & 7;
    int tid = threadIdx.x;
    for (int idx = tid; idx < 1024; idx += 256) {
        int r = idx >> 4, c4 = (idx & 15) << 2;
        float4 v = *(const float4*)(lin + ((size_t)(b * SEQ + s0 + r)) * DIM + h * DHD + c4);
        tile[r][c4 + 0] = v.x; tile[r][c4 + 1] = v.y;
        tile[r][c4 + 2] = v.z; tile[r][c4 + 3] = v.w;
    }
    __syncthreads();
    for (int idx = tid; idx < 2048; idx += 256) {
        int d = idx >> 5, sp = (idx & 31) << 1;
        float v0 = tile[sp][d], v1 = tile[sp + 1][d];
        __nv_bfloat16 h0 = __float2bfloat16(v0), h1 = __float2bfloat16(v1);
        float l0 = v0 - __bfloat162float(h0), l1 = v1 - __bfloat162float(h1);
        size_t o = ((size_t)bh * DHD + d) * SEQ + s0 + sp;
        *(__nv_bfloat162*)(oh + o) = {h0, h1};
        *(__nv_bfloat162*)(ol + o) = {__float2bfloat16(l0), __float2bfloat16(l1)};
    }
}

// ---------------- HMMA flash attention ----------------
// 128 q-rows/CTA (8 warps x 16 rows), causal, cp.async double-buffered K/V tiles.
// Q pre-scaled by 1/8. Outputs bf16 hi/lo in (B,S,D) for the Wo GEMM.
#define AT_STR 72
#define FA_BUF (64*AT_STR)          // elements per operand buffer (4608)
#define FA_STAGE (4*FA_BUF)         // 18432 elements per stage
#define FA_SMEM (2*FA_STAGE*2)      // 73728 bytes

__global__ __launch_bounds__(256)
void fa_kernel(const __nv_bfloat16* __restrict__ Qh, const __nv_bfloat16* __restrict__ Ql,
               const __nv_bfloat16* __restrict__ Kh, const __nv_bfloat16* __restrict__ Kl,
               const __nv_bfloat16* __restrict__ Vh, const __nv_bfloat16* __restrict__ Vl,
               __nv_bfloat16* __restrict__ Ohi, __nv_bfloat16* __restrict__ Olo) {
    extern __shared__ __nv_bfloat16 smb[];
    const uint32_t sbF = smem_u32(smb);

    const int qt = blockIdx.x, bh = blockIdx.y;
    const int tid = threadIdx.x, w = tid >> 5, lane = tid & 31;
    const int g = lane >> 2, tg = lane & 3;

    // ---- stage Q (128 rows hi + lo) into stage-0 region, extract fragments ----
    {
        const __nv_bfloat16* qbh = Qh + ((size_t)bh * SEQ + qt * 128) * DHD;
        const __nv_bfloat16* qbl = Ql + ((size_t)bh * SEQ + qt * 128) * DHD;
        for (int idx = tid; idx < 1024; idx += 256) {
            int r = idx >> 3, c = (idx & 7) << 3;
            *(uint4*)&smb[r * AT_STR + c]        = *(const uint4*)(qbh + r * DHD + c);
            *(uint4*)&smb[9216 + r * AT_STR + c] = *(const uint4*)(qbl + r * DHD + c);
        }
    }
    __syncthreads();
    uint32_t aQh[4][4], aQl[4][4];
    {
        int r0 = w * 16 + g, r1 = r0 + 8;
#pragma unroll
        for (int kc = 0; kc < 4; kc++) {
            int kk = kc * 16 + tg * 2;
            aQh[kc][0] = *(const uint32_t*)&smb[r0 * AT_STR + kk];
            aQh[kc][1] = *(const uint32_t*)&smb[r1 * AT_STR + kk];
            aQh[kc][2] = *(const uint32_t*)&smb[r0 * AT_STR + kk + 8];
            aQh[kc][3] = *(const uint32_t*)&smb[r1 * AT_STR + kk + 8];
            aQl[kc][0] = *(const uint32_t*)&smb[9216 + r0 * AT_STR + kk];
            aQl[kc][1] = *(const uint32_t*)&smb[9216 + r1 * AT_STR + kk];
            aQl[kc][2] = *(const uint32_t*)&smb[9216 + r0 * AT_STR + kk + 8];
            aQl[kc][3] = *(const uint32_t*)&smb[9216 + r1 * AT_STR + kk + 8];
        }
    }
    __syncthreads();

    float accO[8][4] = {};
    float m0 = -1e30f, m1 = -1e30f, l0 = 0.f, l1 = 0.f;
    const int grow0 = qt * 128 + w * 16 + g;
    const int grow1 = grow0 + 8;

    const __nv_bfloat16* kbh = Kh + (size_t)bh * SEQ * DHD;
    const __nv_bfloat16* kbl = Kl + (size_t)bh * SEQ * DHD;
    const __nv_bfloat16* vbh = Vh + (size_t)bh * DHD * SEQ;
    const __nv_bfloat16* vbl = Vl + (size_t)bh * DHD * SEQ;

    const int ntiles = 2 * qt + 2;
    const int cr = tid >> 3, cc = (tid & 7) << 3;   // 32 rows per 256-thread pass? (2 iters below)

    // prologue: stage tile 0 into stage 0
    {
        uint32_t stb = sbF;
        for (int i = 0; i < 2; i++) {
            int idx = tid + i * 256;
            int r = idx >> 3, c = (idx & 7) << 3;
            uint32_t so = stb + (r * AT_STR + c) * 2;
            cp_async16(so,                 kbh + (size_t)r * DHD + c);
            cp_async16(so + FA_BUF * 2,    kbl + (size_t)r * DHD + c);
            cp_async16(so + 2 * FA_BUF * 2, vbh + (size_t)r * SEQ + c);
            cp_async16(so + 3 * FA_BUF * 2, vbl + (size_t)r * SEQ + c);
        }
        CP_COMMIT();
    }
    (void)cr; (void)cc;

    for (int kt = 0; kt < ntiles; kt++) {
        const int cur = kt & 1;
        if (kt + 1 < ntiles) {
            uint32_t stb = sbF + (cur ^ 1) * FA_STAGE * 2;
            for (int i = 0; i < 2; i++) {
                int idx = tid + i * 256;
                int r = idx >> 3, c = (idx & 7) << 3;
                uint32_t so = stb + (r * AT_STR + c) * 2;
                cp_async16(so,                 kbh + (size_t)((kt + 1) * 64 + r) * DHD + c);
                cp_async16(so + FA_BUF * 2,    kbl + (size_t)((kt + 1) * 64 + r) * DHD + c);
                cp_async16(so + 2 * FA_BUF * 2, vbh + (size_t)r * SEQ + (kt + 1) * 64 + c);
                cp_async16(so + 3 * FA_BUF * 2, vbl + (size_t)r * SEQ + (kt + 1) * 64 + c);
            }
            CP_COMMIT();
            CP_WAIT1();
        } else {
            CP_WAIT0();
        }
        __syncthreads();

        const __nv_bfloat16* sKh = smb + cur * FA_STAGE;
        const __nv_bfloat16* sKl = sKh + FA_BUF;
        const __nv_bfloat16* sVh = sKh + 2 * FA_BUF;
        const __nv_bfloat16* sVl = sKh + 3 * FA_BUF;

        // S = Q @ K^T
        float sc[8][4] = {};
#pragma unroll
        for (int nt = 0; nt < 8; nt++) {
            int nr = nt * 8 + g;
#pragma unroll
            for (int kc = 0; kc < 4; kc++) {
                int kk = kc * 16 + tg * 2;
                uint32_t bkh[2], bkl[2];
                bkh[0] = *(const uint32_t*)&sKh[nr * AT_STR + kk];
                bkh[1] = *(const uint32_t*)&sKh[nr * AT_STR + kk + 8];
                bkl[0] = *(const uint32_t*)&sKl[nr * AT_STR + kk];
                bkl[1] = *(const uint32_t*)&sKl[nr * AT_STR + kk + 8];
                mma16816(sc[nt], aQh[kc], bkh);
                mma16816(sc[nt], aQh[kc], bkl);
                mma16816(sc[nt], aQl[kc], bkh);
            }
        }

        // causal mask on the last two tiles
        if (kt >= 2 * qt) {
#pragma unroll
            for (int nt = 0; nt < 8; nt++) {
                int keyg = kt * 64 + nt * 8 + tg * 2;
                if (keyg     > grow0) sc[nt][0] = -1e30f;
                if (keyg + 1 > grow0) sc[nt][1] = -1e30f;
                if (keyg     > grow1) sc[nt][2] = -1e30f;
                if (keyg + 1 > grow1) sc[nt][3] = -1e30f;
            }
        }

        // online softmax
        float mt0 = -1e30f, mt1 = -1e30f;
#pragma unroll
        for (int nt = 0; nt < 8; nt++) {
            mt0 = fmaxf(mt0, fmaxf(sc[nt][0], sc[nt][1]));
            mt1 = fmaxf(mt1, fmaxf(sc[nt][2], sc[nt][3]));
        }
        mt0 = fmaxf(mt0, __shfl_xor_sync(0xffffffffu, mt0, 1));
        mt0 = fmaxf(mt0, __shfl_xor_sync(0xffffffffu, mt0, 2));
        mt1 = fmaxf(mt1, __shfl_xor_sync(0xffffffffu, mt1, 1));
        mt1 = fmaxf(mt1, __shfl_xor_sync(0xffffffffu, mt1, 2));
        float mn0 = fmaxf(m0, mt0), mn1 = fmaxf(m1, mt1);
        float f0 = __expf(m0 - mn0), f1 = __expf(m1 - mn1);
        float s0 = 0.f, s1 = 0.f;
#pragma unroll
        for (int nt = 0; nt < 8; nt++) {
            float p0 = __expf(sc[nt][0] - mn0);
            float p1 = __expf(sc[nt][1] - mn0);
            float p2 = __expf(sc[nt][2] - mn1);
            float p3 = __expf(sc[nt][3] - mn1);
            sc[nt][0] = p0; sc[nt][1] = p1; sc[nt][2] = p2; sc[nt][3] = p3;
            s0 += p0 + p1; s1 += p2 + p3;
        }
        s0 += __shfl_xor_sync(0xffffffffu, s0, 1);
        s0 += __shfl_xor_sync(0xffffffffu, s0, 2);
        s1 += __shfl_xor_sync(0xffffffffu, s1, 1);
        s1 += __shfl_xor_sync(0xffffffffu, s1, 2);
        l0 = l0 * f0 + s0;
        l1 = l1 * f1 + s1;
        m0 = mn0; m1 = mn1;
#pragma unroll
        for (int dt = 0; dt < 8; dt++) {
            accO[dt][0] *= f0; accO[dt][1] *= f0;
            accO[dt][2] *= f1; accO[dt][3] *= f1;
        }

        // O += P @ V (P re-split hi/lo in registers)
#pragma unroll
        for (int j = 0; j < 4; j++) {
            float x00 = sc[2*j][0],   x01 = sc[2*j][1],   x02 = sc[2*j][2],   x03 = sc[2*j][3];
            float x10 = sc[2*j+1][0], x11 = sc[2*j+1][1], x12 = sc[2*j+1][2], x13 = sc[2*j+1][3];
            uint32_t aPh[4], aPl[4];
            aPh[0] = pack_bf16x2(x00, x01);
            aPh[1] = pack_bf16x2(x02, x03);
            aPh[2] = pack_bf16x2(x10, x11);
            aPh[3] = pack_bf16x2(x12, x13);
            __nv_bfloat162* t;
            t = (__nv_bfloat162*)&aPh[0];
            aPl[0] = pack_bf16x2(x00 - __bfloat162float(t->x), x01 - __bfloat162float(t->y));
            t = (__nv_bfloat162*)&aPh[1];
            aPl[1] = pack_bf16x2(x02 - __bfloat162float(t->x), x03 - __bfloat162float(t->y));
            t = (__nv_bfloat162*)&aPh[2];
            aPl[2] = pack_bf16x2(x10 - __bfloat162float(t->x), x11 - __bfloat162float(t->y));
            t = (__nv_bfloat162*)&aPh[3];
            aPl[3] = pack_bf16x2(x12 - __bfloat162float(t->x), x13 - __bfloat162float(t->y));
            int kk = j * 16 + tg * 2;
#pragma unroll
            for (int dt = 0; dt < 8; dt++) {
                int nr = dt * 8 + g;
                uint32_t bvh[2], bvl[2];
                bvh[0] = *(const uint32_t*)&sVh[nr * AT_STR + kk];
                bvh[1] = *(const uint32_t*)&sVh[nr * AT_STR + kk + 8];
                bvl[0] = *(const uint32_t*)&sVl[nr * AT_STR + kk];
                bvl[1] = *(const uint32_t*)&sVl[nr * AT_STR + kk + 8];
                mma16816(accO[dt], aPh, bvh);
                mma16816(accO[dt], aPh, bvl);
                mma16816(accO[dt], aPl, bvh);
            }
        }
        __syncthreads();
    }

    // epilogue -> (B,S,D) bf16 hi/lo
    float il0 = 1.0f / l0, il1 = 1.0f / l1;
    int b = bh >> 3, h = bh & 7;
    size_t row0 = (size_t)b * SEQ + qt * 128 + w * 16 + g;
    size_t row1 = row0 + 8;
#pragma unroll
    for (int dt = 0; dt < 8; dt++) {
        int col = h * DHD + dt * 8 + tg * 2;
        float o0 = accO[dt][0] * il0, o1 = accO[dt][1] * il0;
        float o2 = accO[dt][2] * il1, o3 = accO[dt][3] * il1;
        __nv_bfloat16 h0 = __float2bfloat16(o0), h1 = __float2bfloat16(o1);
        __nv_bfloat16 h2 = __float2bfloat16(o2), h3 = __float2bfloat16(o3);
        *(__nv_bfloat162*)(Ohi + row0 * DIM + col) = {h0, h1};
        *(__nv_bfloat162*)(Ohi + row1 * DIM + col) = {h2, h3};
        *(__nv_bfloat162*)(Olo + row0 * DIM + col) =
            {__float2bfloat16(o0 - __bfloat162float(h0)), __float2bfloat16(o1 - __bfloat162float(h1))};
        *(__nv_bfloat162*)(Olo + row1 * DIM + col) =
            {__float2bfloat16(o2 - __bfloat162float(h2)), __float2bfloat16(o3 - __bfloat162float(h3))};
    }
}

// ---------------- head: logits -> sigmoid probs ----------------
__global__ void head_kernel(const float* __restrict__ X, const float* __restrict__ hw,
                            const float* __restrict__ hb, float* __restrict__ probs) {
    int row = blockIdx.x * 8 + (threadIdx.x >> 5);
    int lane = threadIdx.x & 31;
    const float* xr = X + (size_t)row * DIM;
    float s = 0.f;
    for (int i = lane; i < DIM; i += 32) s = fmaf(xr[i], hw[i], s);
#pragma unroll
    for (int o = 16; o; o >>= 1) s += __shfl_xor_sync(0xffffffffu, s, o);
    if (lane == 0) {
        float logit = s + hb[0];
        probs[row] = 1.0f / (1.0f + expf(-logit));
    }
}

// ---------------- chunking ----------------
__global__ void chunk_kernel(const float* __restrict__ probs, int* __restrict__ ids,
                             int* __restrict__ nch, float* __restrict__ psum) {
    int b = blockIdx.x, t = threadIdx.x;
    __shared__ int flags[SEQ];
    __shared__ float red[256];
    const float* pr = probs + (size_t)b * SEQ;
    float s = 0.f; int any = 0;
    for (int i = t; i < SEQ; i += 256) {
        float p = pr[i];
        int f = (p > 0.5f) ? 1 : 0;
        flags[i] = f; s += p; any |= f;
    }
    red[t] = s;
    __syncthreads();
#pragma unroll
    for (int o = 128; o > 0; o >>= 1) {
        if (t < o) red[t] += red[t + o];
        __syncthreads();
    }
    int anyflag = __syncthreads_or(any);
    if (t == 0) {
        psum[b] = red[0];
        int cur_end = 0, cid = -1;
        for (int tt = 0; tt < SEQ; tt++) {
            if (tt == cur_end) {
                int cap = tt + 16; if (cap > SEQ) cap = SEQ;
                int e = cap;
                for (int ss = tt + 1; ss <= cap; ss++) {
                    int he = anyflag ? flags[ss - 1] : (ss == SEQ - 1);
                    if (he) { e = ss; break; }
                }
                if (e - tt < 3) { e = tt + 3; if (e > SEQ) e = SEQ; }
                cur_end = e; cid++;
            }
            ids[b * SEQ + tt] = cid;
        }
        nch[b] = cid + 1;
    }
}

// ---------------- mask ----------------
__global__ void mask_kernel(const int* __restrict__ ids, float* __restrict__ out) {
    int i4 = blockIdx.x * 256 + threadIdx.x;
    int j = (i4 & 511) << 2;
    int rowIdx = i4 >> 9;
    int b = rowIdx >> 11;
    int idi = ids[rowIdx];
    const int* idr = ids + b * SEQ;
    size_t base = ((size_t)rowIdx << 11) + j;
    out[base + 0] = (idi == idr[j + 0]) ? 1.f : 0.f;
    out[base + 1] = (idi == idr[j + 1]) ? 1.f : 0.f;
    out[base + 2] = (idi == idr[j + 2]) ? 1.f : 0.f;
    out[base + 3] = (idi == idr[j + 3]) ? 1.f : 0.f;
}

__global__ void scalars_kernel(const int* __restrict__ nch, const float* __restrict__ psum,
                               float* __restrict__ out_acl, float* __restrict__ out_cll) {
    float a = 0.f, c = 0.f;
    for (int b = 0; b < NUM_B; b++) {
        a += (float)SEQ / (float)nch[b];
        c += psum[b];
    }
    *out_acl = a * 0.25f;
    *out_cll = c * 0.25f;
}

__global__ void xids_kernel(const int* __restrict__ xids, float* __restrict__ out) {
    int i = blockIdx.x * 256 + threadIdx.x;
    out[i] = (float)xids[i];
}

// ---------------- launch ----------------
extern "C" void kernel_launch(void* const* d_in, const int* in_sizes, int n_in,
                              void* d_out, int out_size) {
    const float* x    = (const float*)d_in[0];
    const int*   xids = (const int*)  d_in[1];
    const float* ln1  = (const float*)d_in[2];
    const float* Wq   = (const float*)d_in[3];
    const float* Wk   = (const float*)d_in[4];
    const float* Wv   = (const float*)d_in[5];
    const float* Wo   = (const float*)d_in[6];
    const float* ln2  = (const float*)d_in[7];
    const float* W1   = (const float*)d_in[8];
    const float* W2   = (const float*)d_in[9];
    const float* hw   = (const float*)d_in[10];
    const float* hb   = (const float*)d_in[11];
    float* out = (float*)d_out;

    float *X, *Ql, *Kl, *Vl, *probs, *psum, *rc, *rs;
    __nv_bfloat16 *Ahi, *Alo, *Ghi, *Glo, *WThi, *WTlo;
    __nv_bfloat16 *Qbh, *Qbl, *Kbh, *Kbl, *Vbh, *Vbl;
    int *ids, *nch;
    cudaGetSymbolAddress((void**)&X,  g_X);
    cudaGetSymbolAddress((void**)&Ql, g_Ql);
    cudaGetSymbolAddress((void**)&Kl, g_Kl);
    cudaGetSymbolAddress((void**)&Vl, g_Vl);
    cudaGetSymbolAddress((void**)&Qbh, g_Qbh);
    cudaGetSymbolAddress((void**)&Qbl, g_Qbl);
    cudaGetSymbolAddress((void**)&Kbh, g_Kbh);
    cudaGetSymbolAddress((void**)&Kbl, g_Kbl);
    cudaGetSymbolAddress((void**)&Vbh, g_Vbh);
    cudaGetSymbolAddress((void**)&Vbl, g_Vbl);
    cudaGetSymbolAddress((void**)&Ahi, g_Ahi);
    cudaGetSymbolAddress((void**)&Alo, g_Alo);
    cudaGetSymbolAddress((void**)&Ghi, g_Ghi);
    cudaGetSymbolAddress((void**)&Glo, g_Glo);
    cudaGetSymbolAddress((void**)&WThi, g_WThi);
    cudaGetSymbolAddress((void**)&WTlo, g_WTlo);
    cudaGetSymbolAddress((void**)&probs, g_probs);
    cudaGetSymbolAddress((void**)&psum,  g_psum);
    cudaGetSymbolAddress((void**)&ids, g_ids);
    cudaGetSymbolAddress((void**)&nch, g_nch);
    cudaGetSymbolAddress((void**)&rc, g_rc);
    cudaGetSymbolAddress((void**)&rs, g_rs);

    cudaFuncSetAttribute(hmma_gemm_kernel<0>, cudaFuncAttributeMaxDynamicSharedMemorySize, GM_SMEM2);
    cudaFuncSetAttribute(hmma_gemm_kernel<1>, cudaFuncAttributeMaxDynamicSharedMemorySize, GM_SMEM2);
    cudaFuncSetAttribute(hmma_gemm_kernel<3>, cudaFuncAttributeMaxDynamicSharedMemorySize, GM_SMEM2);
    cudaFuncSetAttribute(fa_kernel, cudaFuncAttributeMaxDynamicSharedMemorySize, FA_SMEM);

    // weight transpose + split
    for (int l = 0; l < NLAYER; l++) {
        __nv_bfloat16* th = WThi + (size_t)l * WT_LAYER;
        __nv_bfloat16* tl = WTlo + (size_t)l * WT_LAYER;
        wsplit_kernel<<<dim3(16, 16), 256>>>(Wq + (size_t)l * DIM * DIM, th + WT_Q,  tl + WT_Q,  512, 512);
        wsplit_kernel<<<dim3(16, 16), 256>>>(Wk + (size_t)l * DIM * DIM, th + WT_K,  tl + WT_K,  512, 512);
        wsplit_kernel<<<dim3(16, 16), 256>>>(Wv + (size_t)l * DIM * DIM, th + WT_V,  tl + WT_V,  512, 512);
        wsplit_kernel<<<dim3(16, 16), 256>>>(Wo + (size_t)l * DIM * DIM, th + WT_O,  tl + WT_O,  512, 512);
        wsplit_kernel<<<dim3(64, 16), 256>>>(W1 + (size_t)l * DIM * FF,  th + WT_W1, tl + WT_W1, 512, 2048);
        wsplit_kernel<<<dim3(16, 64), 256>>>(W2 + (size_t)l * FF * DIM,  th + WT_W2, tl + WT_W2, 2048, 512);
    }
    rope_table_kernel<<<SEQ, 32>>>(rc, rs);
    cudaMemcpyAsync(X, x, sizeof(float) * (size_t)ROWS * DIM, cudaMemcpyDeviceToDevice, 0);

    dim3 g512(DIM / 128, ROWS / 128);   // (4, 64)
    dim3 gff (FF  / 128, ROWS / 128);   // (16, 64)

    for (int l = 0; l < NLAYER; l++) {
        const __nv_bfloat16* th = WThi + (size_t)l * WT_LAYER;
        const __nv_bfloat16* tl = WTlo + (size_t)l * WT_LAYER;

        rmsnorm_split_kernel<<<ROWS, 256>>>(X, ln1 + l * DIM, Ahi, Alo);
        hmma_gemm_kernel<0><<<g512, 256, GM_SMEM2>>>(Ahi, Alo, th + WT_Q, tl + WT_Q,
                                                     nullptr, Ql, nullptr, nullptr, ROWS, DIM, DIM);
        hmma_gemm_kernel<0><<<g512, 256, GM_SMEM2>>>(Ahi, Alo, th + WT_K, tl + WT_K,
                                                     nullptr, Kl, nullptr, nullptr, ROWS, DIM, DIM);
        hmma_gemm_kernel<0><<<g512, 256, GM_SMEM2>>>(Ahi, Alo, th + WT_V, tl + WT_V,
                                                     nullptr, Vl, nullptr, nullptr, ROWS, DIM, DIM);
        rope_split_kernel<<<ROWS, 256>>>(Ql, Qbh, Qbl, rc, rs, 0.125f);
        rope_split_kernel<<<ROWS, 256>>>(Kl, Kbh, Kbl, rc, rs, 1.0f);
        vtrans_split_kernel<<<dim3(SEQ / 64, NUM_B * NH), 256>>>(Vl, Vbh, Vbl);
        fa_kernel<<<dim3(SEQ / 128, NUM_B * NH), 256, FA_SMEM>>>(Qbh, Qbl, Kbh, Kbl, Vbh, Vbl,
                                                                 Ahi, Alo);
        hmma_gemm_kernel<1><<<g512, 256, GM_SMEM2>>>(Ahi, Alo, th + WT_O, tl + WT_O,
                                                     X, X, nullptr, nullptr, ROWS, DIM, DIM);
        rmsnorm_split_kernel<<<ROWS, 256>>>(X, ln2 + l * DIM, Ahi, Alo);
        hmma_gemm_kernel<3><<<gff, 256, GM_SMEM2>>>(Ahi, Alo, th + WT_W1, tl + WT_W1,
                                                    nullptr, nullptr, Ghi, Glo, ROWS, FF, DIM);
        hmma_gemm_kernel<1><<<g512, 256, GM_SMEM2>>>(Ghi, Glo, th + WT_W2, tl + WT_W2,
                                                     X, X, nullptr, nullptr, ROWS, DIM, FF);
    }

    head_kernel <<<ROWS / 8, 256>>>(X, hw, hb, probs);
    chunk_kernel<<<NUM_B, 256>>>(probs, ids, nch, psum);
    mask_kernel <<<(N_MASK / 4) / 256, 256>>>(ids, out + OFF_MASK);
    scalars_kernel<<<1, 1>>>(nch, psum, out + OFF_ACL, out + OFF_CLL);
    xids_kernel <<<ROWS / 256, 256>>>(xids, out + OFF_IDS);
    cudaMemcpyAsync(out + OFF_XT, X, sizeof(float) * (size_t)ROWS * DIM, cudaMemcpyDeviceToDevice, 0);
}